// round 6
// baseline (speedup 1.0000x reference)
#include <cuda_runtime.h>
#include <math.h>
#include <stdint.h>

#define BB 2
#define SS 2048
#define EE 1024
#define HH 16
#define DKK 64
#define HD (HH*DKK)   // 1024

// -------- scratch (allocation-free rule: __device__ globals) --------
__device__ float g_qh[BB*HH*SS*DKK];   // (B,H,S,DK)
__device__ float g_kh[BB*HH*SS*DKK];
__device__ float g_vh[BB*HH*SS*DKK];
__device__ float g_concat[BB*SS*HD];   // (B*S, H*DK)

// ===================================================================
// mma.sync tf32 helpers (baseline PTX, works on compute_103)
// ===================================================================
__device__ __forceinline__ uint32_t f2tf32(float f) {
    uint32_t r;
    asm("cvt.rna.tf32.f32 %0, %1;" : "=r"(r) : "f"(f));
    return r;
}

__device__ __forceinline__ void mma_tf32(float* d, const uint32_t* a,
                                         const uint32_t* b) {
    asm volatile(
        "mma.sync.aligned.m16n8k8.row.col.f32.tf32.tf32.f32 "
        "{%0,%1,%2,%3}, {%4,%5,%6,%7}, {%8,%9}, {%0,%1,%2,%3};"
        : "+f"(d[0]), "+f"(d[1]), "+f"(d[2]), "+f"(d[3])
        : "r"(a[0]), "r"(a[1]), "r"(a[2]), "r"(a[3]),
          "r"(b[0]), "r"(b[1]));
}

// ===================================================================
// tf32 tensor-core GEMM (R3-verified frag layout; 1 sync per chunk)
// ===================================================================
#define GSTRA 44
#define GSTRB 136
#define ASZ (128*GSTRA)
#define BSZ (32*GSTRB)
#define GEMM_SMEM_BYTES ((2*ASZ + 2*BSZ) * 4)   // 79872

template<int MODE>
__global__ __launch_bounds__(256)
void gemm_mma(const float* __restrict__ A, const float* __restrict__ W,
              const float* __restrict__ bias, float* __restrict__ C,
              int M, int N, int K)
{
    extern __shared__ uint32_t sm[];
    uint32_t* AsBuf[2] = { sm,           sm + ASZ };
    uint32_t* BsBuf[2] = { sm + 2*ASZ,   sm + 2*ASZ + BSZ };

    int tid = threadIdx.x, lane = tid & 31, wid = tid >> 5;
    int bm = blockIdx.y * 128, bn = blockIdx.x * 128;
    int wM = (wid >> 1) * 32, wN = (wid & 1) * 64;
    int g = lane >> 2, c = lane & 3;

    float acc[2][8][4];
#pragma unroll
    for (int mf = 0; mf < 2; mf++)
#pragma unroll
        for (int nf = 0; nf < 8; nf++)
#pragma unroll
            for (int r = 0; r < 4; r++) acc[mf][nf][r] = 0.f;

    const int NC = K / 32;
    int aM = tid >> 3, aK4 = tid & 7;
    int bK = tid >> 5, bN4 = tid & 31;
    float4 aR[4], bR[4];

    // ---- stage chunk 0 ----
#pragma unroll
    for (int it = 0; it < 4; it++) {
        aR[it] = *(const float4*)(A + (size_t)(bm + aM + it*32) * K + aK4 * 4);
        bR[it] = *(const float4*)(W + (size_t)(bK + it*8) * N + bn + bN4 * 4);
    }
#pragma unroll
    for (int it = 0; it < 4; it++) {
        uint4 ta = { f2tf32(aR[it].x), f2tf32(aR[it].y),
                     f2tf32(aR[it].z), f2tf32(aR[it].w) };
        *(uint4*)(AsBuf[0] + (aM + it*32) * GSTRA + aK4 * 4) = ta;
        uint4 tb = { f2tf32(bR[it].x), f2tf32(bR[it].y),
                     f2tf32(bR[it].z), f2tf32(bR[it].w) };
        *(uint4*)(BsBuf[0] + (bK + it*8) * GSTRB + bN4 * 4) = tb;
    }
    __syncthreads();

    for (int i = 0; i < NC; i++) {
        int buf = i & 1;
        if (i + 1 < NC) {
#pragma unroll
            for (int it = 0; it < 4; it++) {
                aR[it] = *(const float4*)(A + (size_t)(bm + aM + it*32) * K
                                          + (i+1) * 32 + aK4 * 4);
                bR[it] = *(const float4*)(W + (size_t)((i+1) * 32 + bK + it*8) * N
                                          + bn + bN4 * 4);
            }
        }

        const uint32_t* as = AsBuf[buf];
        const uint32_t* bs = BsBuf[buf];
#pragma unroll
        for (int ks = 0; ks < 4; ks++) {
            int kb = ks * 8;
            uint32_t af[2][4], bf[8][2];
#pragma unroll
            for (int mf = 0; mf < 2; mf++) {
                int m = wM + mf * 16 + g;
                af[mf][0] = as[(m    ) * GSTRA + kb + c];
                af[mf][1] = as[(m + 8) * GSTRA + kb + c];
                af[mf][2] = as[(m    ) * GSTRA + kb + c + 4];
                af[mf][3] = as[(m + 8) * GSTRA + kb + c + 4];
            }
#pragma unroll
            for (int nf = 0; nf < 8; nf++) {
                int n = wN + nf * 8 + g;
                bf[nf][0] = bs[(kb + c    ) * GSTRB + n];
                bf[nf][1] = bs[(kb + c + 4) * GSTRB + n];
            }
#pragma unroll
            for (int mf = 0; mf < 2; mf++)
#pragma unroll
                for (int nf = 0; nf < 8; nf++)
                    mma_tf32(acc[mf][nf], af[mf], bf[nf]);
        }

        // store next chunk into the other buffer; single sync.
        // Safe: reads of buf^1 finished before the PREVIOUS sync.
        if (i + 1 < NC) {
            int nb = buf ^ 1;
#pragma unroll
            for (int it = 0; it < 4; it++) {
                uint4 ta = { f2tf32(aR[it].x), f2tf32(aR[it].y),
                             f2tf32(aR[it].z), f2tf32(aR[it].w) };
                *(uint4*)(AsBuf[nb] + (aM + it*32) * GSTRA + aK4 * 4) = ta;
                uint4 tb = { f2tf32(bR[it].x), f2tf32(bR[it].y),
                             f2tf32(bR[it].z), f2tf32(bR[it].w) };
                *(uint4*)(BsBuf[nb] + (bK + it*8) * GSTRB + bN4 * 4) = tb;
            }
            __syncthreads();
        }
    }

#pragma unroll
    for (int nf = 0; nf < 8; nf++) {
        int col = bn + wN + nf * 8 + 2 * c;
        float b0 = bias[col], b1 = bias[col + 1];
#pragma unroll
        for (int mf = 0; mf < 2; mf++) {
            int row = bm + wM + mf * 16 + g;
#pragma unroll
            for (int half = 0; half < 2; half++) {
                int r = row + half * 8;
                float2 w;
                w.x = acc[mf][nf][half * 2 + 0] + b0;
                w.y = acc[mf][nf][half * 2 + 1] + b1;
                float* dst;
                if (MODE == 0) {
                    dst = C + (size_t)r * N + col;
                } else {
                    int bI = r >> 11, sI = r & 2047;
                    int hI = col >> 6, dI = col & 63;
                    dst = C + (((size_t)(bI * HH + hI) * SS + sI) * DKK + dI);
                }
                *(float2*)dst = w;
            }
        }
    }
}

// ===================================================================
// Tensor-core flash attention v3.
//  - 128 threads / CTA (4 warps), 64 q-rows per CTA -> 55.5KB smem,
//    4 CTAs/SM: barriers block 4 warps, 4 independent CTAs hide latency.
//  - Q/K smem: column-pair interleaved -> QK^T frag loads are LDS.64,
//    conflict-free (R5-verified).
//  - V smem: plain row-major [kv][d], stride 72 -> PV B-frag scalar
//    loads conflict-free (R4-verified); no transpose STS conflicts.
//  - P stays in registers via quad shuffles (R5-verified, exact).
// ===================================================================
#define QSTR 72
#define AOFF_K   (64*QSTR)                // 4608
#define AOFF_V   (AOFF_K + 64*QSTR)       // 9216
#define AOFF_MSK (AOFF_V + 64*QSTR)       // 13824
#define ATTN_SMEM_BYTES ((AOFF_MSK + 64) * 4)   // 55552

__global__ __launch_bounds__(128, 4)
void attn_mma(const float* __restrict__ qh, const float* __restrict__ kh,
              const float* __restrict__ vh, const int* __restrict__ mask,
              float* __restrict__ scores, float* __restrict__ concat)
{
    extern __shared__ uint32_t sm[];
    uint32_t* Qs = sm;
    uint32_t* Ks = sm + AOFF_K;
    uint32_t* Vs = sm + AOFF_V;
    int*      Mk = (int*)(sm + AOFF_MSK);

    int tid = threadIdx.x, lane = tid & 31, wid = tid >> 5;
    int g = lane >> 2, c = lane & 3;
    int q0 = blockIdx.x * 64;
    int h = blockIdx.y, b = blockIdx.z;
    int wq = wid * 16;

    const float* Qb = qh + (size_t)(b * HH + h) * SS * DKK;
    const float* Kb = kh + (size_t)(b * HH + h) * SS * DKK;
    const float* Vb = vh + (size_t)(b * HH + h) * SS * DKK;
    float* scb = scores + ((size_t)(b * HH + h) * SS + q0) * SS;

    // ---- load Q tile [64][64] -> smem tf32, interleaved cols ----
#pragma unroll
    for (int i = 0; i < 8; i++) {
        int idx = tid + i * 128;
        int row = idx >> 4, c4 = idx & 15;
        float4 v = *(const float4*)(Qb + (size_t)(q0 + row) * DKK + c4 * 4);
        uint32_t* dst = Qs + row * QSTR + (c4 >> 1) * 8 + (c4 & 1);
        dst[0] = f2tf32(v.x); dst[2] = f2tf32(v.y);
        dst[4] = f2tf32(v.z); dst[6] = f2tf32(v.w);
    }

    float m0 = -INFINITY, m1 = -INFINITY, l0 = 0.f, l1 = 0.f;
    float o[8][4];
#pragma unroll
    for (int nf = 0; nf < 8; nf++)
#pragma unroll
        for (int r = 0; r < 4; r++) o[nf][r] = 0.f;

    int rowA = wq + g;
    int qb = lane & 28;                            // quad base lane

    for (int kv0 = 0; kv0 < SS; kv0 += 64) {
        __syncthreads();   // prev iter done reading K/V
        // ---- K tile [64][64] interleaved; V tile plain row-major ----
#pragma unroll
        for (int i = 0; i < 8; i++) {
            int idx = tid + i * 128;
            int row = idx >> 4, c4 = idx & 15;
            float4 kq = *(const float4*)(Kb + (size_t)(kv0 + row) * DKK + c4 * 4);
            uint32_t* dst = Ks + row * QSTR + (c4 >> 1) * 8 + (c4 & 1);
            dst[0] = f2tf32(kq.x); dst[2] = f2tf32(kq.y);
            dst[4] = f2tf32(kq.z); dst[6] = f2tf32(kq.w);
            float4 vq = *(const float4*)(Vb + (size_t)(kv0 + row) * DKK + c4 * 4);
            uint4 tv = { f2tf32(vq.x), f2tf32(vq.y), f2tf32(vq.z), f2tf32(vq.w) };
            *(uint4*)(Vs + row * QSTR + c4 * 4) = tv;
        }
        if (tid < 64) Mk[tid] = mask[b * SS + kv0 + tid];
        __syncthreads();

        // ---- S = Q @ K^T : per warp 16q x 64kv ----
        float s[8][4];
#pragma unroll
        for (int nf = 0; nf < 8; nf++)
#pragma unroll
            for (int r = 0; r < 4; r++) s[nf][r] = 0.f;

#pragma unroll
        for (int ks = 0; ks < 8; ks++) {
            const uint32_t* qp = Qs + rowA * QSTR + ks * 8 + 2 * c;
            uint2 a01 = *(const uint2*)qp;
            uint2 a23 = *(const uint2*)(qp + 8 * QSTR);
            uint32_t af[4] = { a01.x, a23.x, a01.y, a23.y };
#pragma unroll
            for (int nf = 0; nf < 8; nf++) {
                int n = nf * 8 + g;
                uint2 bu = *(const uint2*)(Ks + n * QSTR + ks * 8 + 2 * c);
                uint32_t bf[2] = { bu.x, bu.y };
                mma_tf32(s[nf], af, bf);
            }
        }

        // ---- mask + scale + write scores + row max ----
        float mx0 = -INFINITY, mx1 = -INFINITY;
#pragma unroll
        for (int nf = 0; nf < 8; nf++) {
            int col = nf * 8 + 2 * c;
            int2 mv = *(const int2*)(Mk + col);
            s[nf][0] = mv.x ? s[nf][0] * 0.125f : -1e9f;
            s[nf][1] = mv.y ? s[nf][1] * 0.125f : -1e9f;
            s[nf][2] = mv.x ? s[nf][2] * 0.125f : -1e9f;
            s[nf][3] = mv.y ? s[nf][3] * 0.125f : -1e9f;
            float2 w0 = { s[nf][0], s[nf][1] };
            float2 w1 = { s[nf][2], s[nf][3] };
            *(float2*)(scb + (size_t)(rowA    ) * SS + kv0 + col) = w0;
            *(float2*)(scb + (size_t)(rowA + 8) * SS + kv0 + col) = w1;
            mx0 = fmaxf(mx0, fmaxf(s[nf][0], s[nf][1]));
            mx1 = fmaxf(mx1, fmaxf(s[nf][2], s[nf][3]));
        }
        mx0 = fmaxf(mx0, __shfl_xor_sync(0xFFFFFFFFu, mx0, 1));
        mx0 = fmaxf(mx0, __shfl_xor_sync(0xFFFFFFFFu, mx0, 2));
        mx1 = fmaxf(mx1, __shfl_xor_sync(0xFFFFFFFFu, mx1, 1));
        mx1 = fmaxf(mx1, __shfl_xor_sync(0xFFFFFFFFu, mx1, 2));

        float mn0 = fmaxf(m0, mx0), mn1 = fmaxf(m1, mx1);
        float a0 = __expf(m0 - mn0), a1 = __expf(m1 - mn1);
        m0 = mn0; m1 = mn1;

        // ---- exp + row sums, convert P to tf32 bits in-place ----
        float sum0 = 0.f, sum1 = 0.f;
#pragma unroll
        for (int nf = 0; nf < 8; nf++) {
            float p0 = __expf(s[nf][0] - mn0);
            float p1 = __expf(s[nf][1] - mn0);
            float p2 = __expf(s[nf][2] - mn1);
            float p3 = __expf(s[nf][3] - mn1);
            sum0 += p0 + p1;
            sum1 += p2 + p3;
            s[nf][0] = __uint_as_float(f2tf32(p0));
            s[nf][1] = __uint_as_float(f2tf32(p1));
            s[nf][2] = __uint_as_float(f2tf32(p2));
            s[nf][3] = __uint_as_float(f2tf32(p3));
        }
        sum0 += __shfl_xor_sync(0xFFFFFFFFu, sum0, 1);
        sum0 += __shfl_xor_sync(0xFFFFFFFFu, sum0, 2);
        sum1 += __shfl_xor_sync(0xFFFFFFFFu, sum1, 1);
        sum1 += __shfl_xor_sync(0xFFFFFFFFu, sum1, 2);
        l0 = l0 * a0 + sum0;
        l1 = l1 * a1 + sum1;

        // ---- rescale O ----
#pragma unroll
        for (int nf = 0; nf < 8; nf++) {
            o[nf][0] *= a0; o[nf][1] *= a0;
            o[nf][2] *= a1; o[nf][3] *= a1;
        }

        // ---- O += P @ V : P A-frags built by quad shuffles ----
        int src  = qb + (c >> 1);
        int src2 = src + 2;
        bool odd = (c & 1);
#pragma unroll
        for (int ks = 0; ks < 8; ks++) {
            float x0 = __shfl_sync(0xFFFFFFFFu, s[ks][0], src);
            float x1 = __shfl_sync(0xFFFFFFFFu, s[ks][1], src);
            float x2 = __shfl_sync(0xFFFFFFFFu, s[ks][2], src);
            float x3 = __shfl_sync(0xFFFFFFFFu, s[ks][3], src);
            float y0 = __shfl_sync(0xFFFFFFFFu, s[ks][0], src2);
            float y1 = __shfl_sync(0xFFFFFFFFu, s[ks][1], src2);
            float y2 = __shfl_sync(0xFFFFFFFFu, s[ks][2], src2);
            float y3 = __shfl_sync(0xFFFFFFFFu, s[ks][3], src2);
            uint32_t af[4];
            af[0] = __float_as_uint(odd ? x1 : x0);
            af[1] = __float_as_uint(odd ? x3 : x2);
            af[2] = __float_as_uint(odd ? y1 : y0);
            af[3] = __float_as_uint(odd ? y3 : y2);
            int kb = ks * 8;
#pragma unroll
            for (int nf = 0; nf < 8; nf++) {
                int n = nf * 8 + g;
                uint32_t bf[2];
                bf[0] = Vs[(kb + c    ) * QSTR + n];
                bf[1] = Vs[(kb + c + 4) * QSTR + n];
                mma_tf32(o[nf], af, bf);
            }
        }
    }

    // ---- finalize: /l, write concat ----
    float inv0 = 1.f / l0, inv1 = 1.f / l1;
#pragma unroll
    for (int nf = 0; nf < 8; nf++) {
        int d = nf * 8 + 2 * c;
        float2 w0 = { o[nf][0] * inv0, o[nf][1] * inv0 };
        float2 w1 = { o[nf][2] * inv1, o[nf][3] * inv1 };
        *(float2*)(concat + (size_t)(b * SS + q0 + rowA    ) * HD + h * DKK + d) = w0;
        *(float2*)(concat + (size_t)(b * SS + q0 + rowA + 8) * HD + h * DKK + d) = w1;
    }
}

// ===================================================================
extern "C" void kernel_launch(void* const* d_in, const int* in_sizes, int n_in,
                              void* d_out, int out_size)
{
    const float* q   = (const float*)d_in[0];
    const float* k   = (const float*)d_in[1];
    const float* v   = (const float*)d_in[2];
    const int*   msk = (const int*)  d_in[3];
    const float* Wq  = (const float*)d_in[4];
    const float* bq  = (const float*)d_in[5];
    const float* Wk  = (const float*)d_in[6];
    const float* bk  = (const float*)d_in[7];
    const float* Wv  = (const float*)d_in[8];
    const float* bv  = (const float*)d_in[9];
    const float* Wo  = (const float*)d_in[10];
    const float* bo  = (const float*)d_in[11];

    float* out    = (float*)d_out;              // (B,S,E)
    float* scores = out + (size_t)BB * SS * EE; // (B,H,S,S)

    float *p_qh, *p_kh, *p_vh, *p_cc;
    cudaGetSymbolAddress((void**)&p_qh, g_qh);
    cudaGetSymbolAddress((void**)&p_kh, g_kh);
    cudaGetSymbolAddress((void**)&p_vh, g_vh);
    cudaGetSymbolAddress((void**)&p_cc, g_concat);

    cudaFuncSetAttribute(gemm_mma<0>, cudaFuncAttributeMaxDynamicSharedMemorySize,
                         GEMM_SMEM_BYTES);
    cudaFuncSetAttribute(gemm_mma<1>, cudaFuncAttributeMaxDynamicSharedMemorySize,
                         GEMM_SMEM_BYTES);
    cudaFuncSetAttribute(attn_mma, cudaFuncAttributeMaxDynamicSharedMemorySize,
                         ATTN_SMEM_BYTES);

    dim3 gProj(HD / 128, (BB * SS) / 128);  // (8, 32)
    gemm_mma<1><<<gProj, 256, GEMM_SMEM_BYTES>>>(q, Wq, bq, p_qh, BB * SS, HD, EE);
    gemm_mma<1><<<gProj, 256, GEMM_SMEM_BYTES>>>(k, Wk, bk, p_kh, BB * SS, HD, EE);
    gemm_mma<1><<<gProj, 256, GEMM_SMEM_BYTES>>>(v, Wv, bv, p_vh, BB * SS, HD, EE);

    dim3 gAttn(SS / 64, HH, BB);            // (32, 16, 2)
    attn_mma<<<gAttn, 128, ATTN_SMEM_BYTES>>>(p_qh, p_kh, p_vh, msk, scores, p_cc);

    dim3 gOut(EE / 128, (BB * SS) / 128);   // (8, 32)
    gemm_mma<0><<<gOut, 256, GEMM_SMEM_BYTES>>>(p_cc, Wo, bo, out, BB * SS, EE, HD);
}

// round 7
// speedup vs baseline: 1.3273x; 1.3273x over previous
#include <cuda_runtime.h>
#include <math.h>
#include <stdint.h>

#define BB 2
#define SS 2048
#define EE 1024
#define HH 16
#define DKK 64
#define HD (HH*DKK)   // 1024

// -------- scratch (allocation-free rule: __device__ globals) --------
__device__ float g_qh[BB*HH*SS*DKK];   // (B,H,S,DK)
__device__ float g_kh[BB*HH*SS*DKK];
__device__ float g_vh[BB*HH*SS*DKK];
__device__ float g_concat[BB*SS*HD];   // (B*S, H*DK)

// ===================================================================
// mma helpers (baseline PTX, works on compute_103)
// ===================================================================
__device__ __forceinline__ uint32_t f2tf32(float f) {
    uint32_t r;
    asm("cvt.rna.tf32.f32 %0, %1;" : "=r"(r) : "f"(f));
    return r;
}

__device__ __forceinline__ void mma_tf32(float* d, const uint32_t* a,
                                         const uint32_t* b) {
    asm volatile(
        "mma.sync.aligned.m16n8k8.row.col.f32.tf32.tf32.f32 "
        "{%0,%1,%2,%3}, {%4,%5,%6,%7}, {%8,%9}, {%0,%1,%2,%3};"
        : "+f"(d[0]), "+f"(d[1]), "+f"(d[2]), "+f"(d[3])
        : "r"(a[0]), "r"(a[1]), "r"(a[2]), "r"(a[3]),
          "r"(b[0]), "r"(b[1]));
}

// fp16 mma m16n8k16, fp32 accumulate
__device__ __forceinline__ void mma_f16(float* d, const uint32_t* a,
                                        const uint32_t* b) {
    asm volatile(
        "mma.sync.aligned.m16n8k16.row.col.f32.f16.f16.f32 "
        "{%0,%1,%2,%3}, {%4,%5,%6,%7}, {%8,%9}, {%0,%1,%2,%3};"
        : "+f"(d[0]), "+f"(d[1]), "+f"(d[2]), "+f"(d[3])
        : "r"(a[0]), "r"(a[1]), "r"(a[2]), "r"(a[3]),
          "r"(b[0]), "r"(b[1]));
}

__device__ __forceinline__ uint32_t pack_h2(float lo, float hi) {
    uint32_t r;
    asm("cvt.rn.f16x2.f32 %0, %1, %2;" : "=r"(r) : "f"(hi), "f"(lo));
    return r;
}

__device__ __forceinline__ void ldm_x4(uint32_t* r, uint32_t saddr) {
    asm volatile(
        "ldmatrix.sync.aligned.m8n8.x4.shared.b16 {%0,%1,%2,%3}, [%4];"
        : "=r"(r[0]), "=r"(r[1]), "=r"(r[2]), "=r"(r[3]) : "r"(saddr));
}

__device__ __forceinline__ void ldm_x4_t(uint32_t* r, uint32_t saddr) {
    asm volatile(
        "ldmatrix.sync.aligned.m8n8.x4.trans.shared.b16 {%0,%1,%2,%3}, [%4];"
        : "=r"(r[0]), "=r"(r[1]), "=r"(r[2]), "=r"(r[3]) : "r"(saddr));
}

// ===================================================================
// tf32 tensor-core GEMM (R3-verified; double-sync pipeline)
// ===================================================================
#define GSTRA 44
#define GSTRB 136
#define ASZ (128*GSTRA)
#define BSZ (32*GSTRB)
#define GEMM_SMEM_BYTES ((2*ASZ + 2*BSZ) * 4)   // 79872

template<int MODE>
__global__ __launch_bounds__(256)
void gemm_mma(const float* __restrict__ A, const float* __restrict__ W,
              const float* __restrict__ bias, float* __restrict__ C,
              int M, int N, int K)
{
    extern __shared__ uint32_t sm[];
    uint32_t* AsBuf[2] = { sm,           sm + ASZ };
    uint32_t* BsBuf[2] = { sm + 2*ASZ,   sm + 2*ASZ + BSZ };

    int tid = threadIdx.x, lane = tid & 31, wid = tid >> 5;
    int bm = blockIdx.y * 128, bn = blockIdx.x * 128;
    int wM = (wid >> 1) * 32, wN = (wid & 1) * 64;
    int g = lane >> 2, c = lane & 3;

    float acc[2][8][4];
#pragma unroll
    for (int mf = 0; mf < 2; mf++)
#pragma unroll
        for (int nf = 0; nf < 8; nf++)
#pragma unroll
            for (int r = 0; r < 4; r++) acc[mf][nf][r] = 0.f;

    const int NC = K / 32;
    int aM = tid >> 3, aK4 = tid & 7;
    int bK = tid >> 5, bN4 = tid & 31;
    float4 aR[4], bR[4];

#pragma unroll
    for (int it = 0; it < 4; it++) {
        aR[it] = *(const float4*)(A + (size_t)(bm + aM + it*32) * K + aK4 * 4);
        bR[it] = *(const float4*)(W + (size_t)(bK + it*8) * N + bn + bN4 * 4);
    }
#pragma unroll
    for (int it = 0; it < 4; it++) {
        uint4 ta = { f2tf32(aR[it].x), f2tf32(aR[it].y),
                     f2tf32(aR[it].z), f2tf32(aR[it].w) };
        *(uint4*)(AsBuf[0] + (aM + it*32) * GSTRA + aK4 * 4) = ta;
        uint4 tb = { f2tf32(bR[it].x), f2tf32(bR[it].y),
                     f2tf32(bR[it].z), f2tf32(bR[it].w) };
        *(uint4*)(BsBuf[0] + (bK + it*8) * GSTRB + bN4 * 4) = tb;
    }
    __syncthreads();

    for (int i = 0; i < NC; i++) {
        int buf = i & 1;
        if (i + 1 < NC) {
#pragma unroll
            for (int it = 0; it < 4; it++) {
                aR[it] = *(const float4*)(A + (size_t)(bm + aM + it*32) * K
                                          + (i+1) * 32 + aK4 * 4);
                bR[it] = *(const float4*)(W + (size_t)((i+1) * 32 + bK + it*8) * N
                                          + bn + bN4 * 4);
            }
        }

        const uint32_t* as = AsBuf[buf];
        const uint32_t* bs = BsBuf[buf];
#pragma unroll
        for (int ks = 0; ks < 4; ks++) {
            int kb = ks * 8;
            uint32_t af[2][4], bf[8][2];
#pragma unroll
            for (int mf = 0; mf < 2; mf++) {
                int m = wM + mf * 16 + g;
                af[mf][0] = as[(m    ) * GSTRA + kb + c];
                af[mf][1] = as[(m + 8) * GSTRA + kb + c];
                af[mf][2] = as[(m    ) * GSTRA + kb + c + 4];
                af[mf][3] = as[(m + 8) * GSTRA + kb + c + 4];
            }
#pragma unroll
            for (int nf = 0; nf < 8; nf++) {
                int n = wN + nf * 8 + g;
                bf[nf][0] = bs[(kb + c    ) * GSTRB + n];
                bf[nf][1] = bs[(kb + c + 4) * GSTRB + n];
            }
#pragma unroll
            for (int mf = 0; mf < 2; mf++)
#pragma unroll
                for (int nf = 0; nf < 8; nf++)
                    mma_tf32(acc[mf][nf], af[mf], bf[nf]);
        }

        if (i + 1 < NC) {
            __syncthreads();
            int nb = buf ^ 1;
#pragma unroll
            for (int it = 0; it < 4; it++) {
                uint4 ta = { f2tf32(aR[it].x), f2tf32(aR[it].y),
                             f2tf32(aR[it].z), f2tf32(aR[it].w) };
                *(uint4*)(AsBuf[nb] + (aM + it*32) * GSTRA + aK4 * 4) = ta;
                uint4 tb = { f2tf32(bR[it].x), f2tf32(bR[it].y),
                             f2tf32(bR[it].z), f2tf32(bR[it].w) };
                *(uint4*)(BsBuf[nb] + (bK + it*8) * GSTRB + bN4 * 4) = tb;
            }
            __syncthreads();
        }
    }

#pragma unroll
    for (int nf = 0; nf < 8; nf++) {
        int col = bn + wN + nf * 8 + 2 * c;
        float b0 = bias[col], b1 = bias[col + 1];
#pragma unroll
        for (int mf = 0; mf < 2; mf++) {
            int row = bm + wM + mf * 16 + g;
#pragma unroll
            for (int half = 0; half < 2; half++) {
                int r = row + half * 8;
                float2 w;
                w.x = acc[mf][nf][half * 2 + 0] + b0;
                w.y = acc[mf][nf][half * 2 + 1] + b1;
                float* dst;
                if (MODE == 0) {
                    dst = C + (size_t)r * N + col;
                } else {
                    int bI = r >> 11, sI = r & 2047;
                    int hI = col >> 6, dI = col & 63;
                    dst = C + (((size_t)(bI * HH + hI) * SS + sI) * DKK + dI);
                }
                *(float2*)dst = w;
            }
        }
    }
}

// ===================================================================
// Tensor-core flash attention v4 — fp16 m16n8k16 + ldmatrix.
//  - 256 threads, 128 q-rows/CTA (R5 structure, best measured).
//  - Q/K/V smem as fp16x2 rows (32 words + 4 pad = stride 36).
//  - All operand loads via ldmatrix.x4 (V row-major via .trans).
//  - P@V A-frags come DIRECTLY from the S accumulator layout:
//    pack_f16x2 of accum regs — no shuffles, no smem for P.
// ===================================================================
#define HSTR 36
#define HOFF_K   (128*HSTR)               // 4608
#define HOFF_V   (HOFF_K + 64*HSTR)       // 6912
#define HOFF_MSK (HOFF_V + 64*HSTR)       // 9216
#define ATTN_SMEM_BYTES ((HOFF_MSK + 64) * 4)   // 37120

__global__ __launch_bounds__(256, 2)
void attn_mma(const float* __restrict__ qh, const float* __restrict__ kh,
              const float* __restrict__ vh, const int* __restrict__ mask,
              float* __restrict__ scores, float* __restrict__ concat)
{
    extern __shared__ uint32_t sm[];
    uint32_t* Qs = sm;
    uint32_t* Ks = sm + HOFF_K;
    uint32_t* Vs = sm + HOFF_V;
    int*      Mk = (int*)(sm + HOFF_MSK);

    int tid = threadIdx.x, lane = tid & 31, wid = tid >> 5;
    int g = lane >> 2, c = lane & 3;
    int q0 = blockIdx.x * 128;
    int h = blockIdx.y, b = blockIdx.z;
    int wq = wid * 16;

    const float* Qb = qh + (size_t)(b * HH + h) * SS * DKK;
    const float* Kb = kh + (size_t)(b * HH + h) * SS * DKK;
    const float* Vb = vh + (size_t)(b * HH + h) * SS * DKK;
    float* scb = scores + ((size_t)(b * HH + h) * SS + q0) * SS;

    // ---- load Q tile [128][64] -> smem fp16x2 ----
#pragma unroll
    for (int i = 0; i < 8; i++) {
        int idx = tid + i * 256;
        int row = idx >> 4, c4 = idx & 15;
        float4 v = *(const float4*)(Qb + (size_t)(q0 + row) * DKK + c4 * 4);
        uint2 hh = { pack_h2(v.x, v.y), pack_h2(v.z, v.w) };
        *(uint2*)(Qs + row * HSTR + c4 * 2) = hh;
    }

    // ldmatrix lane-address components (precomputed)
    int qrow  = wq + (lane & 7) + 8 * ((lane >> 3) & 1);
    int qcsel = 4 * (lane >> 4);
    uint32_t qaddr = (uint32_t)__cvta_generic_to_shared(Qs + qrow * HSTR + qcsel);

    int krowoff = (lane & 7) + 8 * (lane >> 4);
    int kwsel   = 4 * ((lane >> 3) & 1);
    uint32_t kaddr0 = (uint32_t)__cvta_generic_to_shared(Ks + krowoff * HSTR + kwsel);

    int vrowoff = (lane & 7) + 8 * ((lane >> 3) & 1);
    int vwsel   = 4 * (lane >> 4);
    uint32_t vaddr0 = (uint32_t)__cvta_generic_to_shared(Vs + vrowoff * HSTR + vwsel);

    float m0 = -INFINITY, m1 = -INFINITY, l0 = 0.f, l1 = 0.f;
    float o[8][4];
#pragma unroll
    for (int nf = 0; nf < 8; nf++)
#pragma unroll
        for (int r = 0; r < 4; r++) o[nf][r] = 0.f;

    int rowA = wq + g;

    for (int kv0 = 0; kv0 < SS; kv0 += 64) {
        __syncthreads();   // prev iter done reading K/V
        // ---- K, V tiles [64][64] -> fp16x2 rows ----
#pragma unroll
        for (int i = 0; i < 4; i++) {
            int idx = tid + i * 256;
            int row = idx >> 4, c4 = idx & 15;
            float4 kq = *(const float4*)(Kb + (size_t)(kv0 + row) * DKK + c4 * 4);
            uint2 hk = { pack_h2(kq.x, kq.y), pack_h2(kq.z, kq.w) };
            *(uint2*)(Ks + row * HSTR + c4 * 2) = hk;
            float4 vq = *(const float4*)(Vb + (size_t)(kv0 + row) * DKK + c4 * 4);
            uint2 hv = { pack_h2(vq.x, vq.y), pack_h2(vq.z, vq.w) };
            *(uint2*)(Vs + row * HSTR + c4 * 2) = hv;
        }
        if (tid < 64) Mk[tid] = mask[b * SS + kv0 + tid];
        __syncthreads();

        // ---- S = Q @ K^T : 4 k16-steps, 8 kv-blocks ----
        float s[8][4];
#pragma unroll
        for (int nf = 0; nf < 8; nf++)
#pragma unroll
            for (int r = 0; r < 4; r++) s[nf][r] = 0.f;

#pragma unroll
        for (int ks = 0; ks < 4; ks++) {
            uint32_t aq[4];
            ldm_x4(aq, qaddr + ks * 32);              // 8 words = 32B per k16
#pragma unroll
            for (int nfp = 0; nfp < 4; nfp++) {
                uint32_t kb[4];
                ldm_x4(kb, kaddr0 + nfp * (16 * HSTR * 4) + ks * 32);
                mma_f16(s[2*nfp    ], aq, kb + 0);
                mma_f16(s[2*nfp + 1], aq, kb + 2);
            }
        }

        // ---- mask + scale + write scores + row max ----
        float mx0 = -INFINITY, mx1 = -INFINITY;
#pragma unroll
        for (int nf = 0; nf < 8; nf++) {
            int col = nf * 8 + 2 * c;
            int2 mv = *(const int2*)(Mk + col);
            s[nf][0] = mv.x ? s[nf][0] * 0.125f : -1e9f;
            s[nf][1] = mv.y ? s[nf][1] * 0.125f : -1e9f;
            s[nf][2] = mv.x ? s[nf][2] * 0.125f : -1e9f;
            s[nf][3] = mv.y ? s[nf][3] * 0.125f : -1e9f;
            float2 w0 = { s[nf][0], s[nf][1] };
            float2 w1 = { s[nf][2], s[nf][3] };
            *(float2*)(scb + (size_t)(rowA    ) * SS + kv0 + col) = w0;
            *(float2*)(scb + (size_t)(rowA + 8) * SS + kv0 + col) = w1;
            mx0 = fmaxf(mx0, fmaxf(s[nf][0], s[nf][1]));
            mx1 = fmaxf(mx1, fmaxf(s[nf][2], s[nf][3]));
        }
        mx0 = fmaxf(mx0, __shfl_xor_sync(0xFFFFFFFFu, mx0, 1));
        mx0 = fmaxf(mx0, __shfl_xor_sync(0xFFFFFFFFu, mx0, 2));
        mx1 = fmaxf(mx1, __shfl_xor_sync(0xFFFFFFFFu, mx1, 1));
        mx1 = fmaxf(mx1, __shfl_xor_sync(0xFFFFFFFFu, mx1, 2));

        float mn0 = fmaxf(m0, mx0), mn1 = fmaxf(m1, mx1);
        float a0 = __expf(m0 - mn0), a1 = __expf(m1 - mn1);
        m0 = mn0; m1 = mn1;

        // ---- exp + row sums (fp32), P stays in s[] ----
        float sum0 = 0.f, sum1 = 0.f;
#pragma unroll
        for (int nf = 0; nf < 8; nf++) {
            s[nf][0] = __expf(s[nf][0] - mn0);
            s[nf][1] = __expf(s[nf][1] - mn0);
            s[nf][2] = __expf(s[nf][2] - mn1);
            s[nf][3] = __expf(s[nf][3] - mn1);
            sum0 += s[nf][0] + s[nf][1];
            sum1 += s[nf][2] + s[nf][3];
        }
        sum0 += __shfl_xor_sync(0xFFFFFFFFu, sum0, 1);
        sum0 += __shfl_xor_sync(0xFFFFFFFFu, sum0, 2);
        sum1 += __shfl_xor_sync(0xFFFFFFFFu, sum1, 1);
        sum1 += __shfl_xor_sync(0xFFFFFFFFu, sum1, 2);
        l0 = l0 * a0 + sum0;
        l1 = l1 * a1 + sum1;

        // ---- rescale O ----
#pragma unroll
        for (int nf = 0; nf < 8; nf++) {
            o[nf][0] *= a0; o[nf][1] *= a0;
            o[nf][2] *= a1; o[nf][3] *= a1;
        }

        // ---- O += P @ V : A-frags straight from accumulators ----
#pragma unroll
        for (int ks = 0; ks < 4; ks++) {
            uint32_t ap[4];
            ap[0] = pack_h2(s[2*ks    ][0], s[2*ks    ][1]);
            ap[1] = pack_h2(s[2*ks    ][2], s[2*ks    ][3]);
            ap[2] = pack_h2(s[2*ks + 1][0], s[2*ks + 1][1]);
            ap[3] = pack_h2(s[2*ks + 1][2], s[2*ks + 1][3]);
#pragma unroll
            for (int nfp = 0; nfp < 4; nfp++) {
                uint32_t vb[4];
                ldm_x4_t(vb, vaddr0 + ks * (16 * HSTR * 4) + nfp * 32);
                mma_f16(o[2*nfp    ], ap, vb + 0);
                mma_f16(o[2*nfp + 1], ap, vb + 2);
            }
        }
    }

    // ---- finalize: /l, write concat ----
    float inv0 = 1.f / l0, inv1 = 1.f / l1;
#pragma unroll
    for (int nf = 0; nf < 8; nf++) {
        int d = nf * 8 + 2 * c;
        float2 w0 = { o[nf][0] * inv0, o[nf][1] * inv0 };
        float2 w1 = { o[nf][2] * inv1, o[nf][3] * inv1 };
        *(float2*)(concat + (size_t)(b * SS + q0 + rowA    ) * HD + h * DKK + d) = w0;
        *(float2*)(concat + (size_t)(b * SS + q0 + rowA + 8) * HD + h * DKK + d) = w1;
    }
}

// ===================================================================
extern "C" void kernel_launch(void* const* d_in, const int* in_sizes, int n_in,
                              void* d_out, int out_size)
{
    const float* q   = (const float*)d_in[0];
    const float* k   = (const float*)d_in[1];
    const float* v   = (const float*)d_in[2];
    const int*   msk = (const int*)  d_in[3];
    const float* Wq  = (const float*)d_in[4];
    const float* bq  = (const float*)d_in[5];
    const float* Wk  = (const float*)d_in[6];
    const float* bk  = (const float*)d_in[7];
    const float* Wv  = (const float*)d_in[8];
    const float* bv  = (const float*)d_in[9];
    const float* Wo  = (const float*)d_in[10];
    const float* bo  = (const float*)d_in[11];

    float* out    = (float*)d_out;              // (B,S,E)
    float* scores = out + (size_t)BB * SS * EE; // (B,H,S,S)

    float *p_qh, *p_kh, *p_vh, *p_cc;
    cudaGetSymbolAddress((void**)&p_qh, g_qh);
    cudaGetSymbolAddress((void**)&p_kh, g_kh);
    cudaGetSymbolAddress((void**)&p_vh, g_vh);
    cudaGetSymbolAddress((void**)&p_cc, g_concat);

    cudaFuncSetAttribute(gemm_mma<0>, cudaFuncAttributeMaxDynamicSharedMemorySize,
                         GEMM_SMEM_BYTES);
    cudaFuncSetAttribute(gemm_mma<1>, cudaFuncAttributeMaxDynamicSharedMemorySize,
                         GEMM_SMEM_BYTES);
    cudaFuncSetAttribute(attn_mma, cudaFuncAttributeMaxDynamicSharedMemorySize,
                         ATTN_SMEM_BYTES);

    dim3 gProj(HD / 128, (BB * SS) / 128);  // (8, 32)
    gemm_mma<1><<<gProj, 256, GEMM_SMEM_BYTES>>>(q, Wq, bq, p_qh, BB * SS, HD, EE);
    gemm_mma<1><<<gProj, 256, GEMM_SMEM_BYTES>>>(k, Wk, bk, p_kh, BB * SS, HD, EE);
    gemm_mma<1><<<gProj, 256, GEMM_SMEM_BYTES>>>(v, Wv, bv, p_vh, BB * SS, HD, EE);

    dim3 gAttn(SS / 128, HH, BB);           // (16, 16, 2)
    attn_mma<<<gAttn, 256, ATTN_SMEM_BYTES>>>(p_qh, p_kh, p_vh, msk, scores, p_cc);

    dim3 gOut(EE / 128, (BB * SS) / 128);   // (8, 32)
    gemm_mma<0><<<gOut, 256, GEMM_SMEM_BYTES>>>(p_cc, Wo, bo, out, BB * SS, EE, HD);
}

// round 8
// speedup vs baseline: 1.7908x; 1.3492x over previous
#include <cuda_runtime.h>
#include <math.h>
#include <stdint.h>

#define BB 2
#define SS 2048
#define EE 1024
#define HH 16
#define DKK 64
#define HD (HH*DKK)   // 1024

// -------- scratch (allocation-free rule: __device__ globals) --------
__device__ float g_qh[BB*HH*SS*DKK];   // (B,H,S,DK)
__device__ float g_kh[BB*HH*SS*DKK];
__device__ float g_vh[BB*HH*SS*DKK];
__device__ float g_concat[BB*SS*HD];   // (B*S, H*DK)

// ===================================================================
// mma helpers (baseline PTX, works on compute_103)
// ===================================================================
// fp16 mma m16n8k16, fp32 accumulate
__device__ __forceinline__ void mma_f16(float* d, const uint32_t* a,
                                        const uint32_t* b) {
    asm volatile(
        "mma.sync.aligned.m16n8k16.row.col.f32.f16.f16.f32 "
        "{%0,%1,%2,%3}, {%4,%5,%6,%7}, {%8,%9}, {%0,%1,%2,%3};"
        : "+f"(d[0]), "+f"(d[1]), "+f"(d[2]), "+f"(d[3])
        : "r"(a[0]), "r"(a[1]), "r"(a[2]), "r"(a[3]),
          "r"(b[0]), "r"(b[1]));
}

__device__ __forceinline__ uint32_t pack_h2(float lo, float hi) {
    uint32_t r;
    asm("cvt.rn.f16x2.f32 %0, %1, %2;" : "=r"(r) : "f"(hi), "f"(lo));
    return r;
}

__device__ __forceinline__ void ldm_x4(uint32_t* r, uint32_t saddr) {
    asm volatile(
        "ldmatrix.sync.aligned.m8n8.x4.shared.b16 {%0,%1,%2,%3}, [%4];"
        : "=r"(r[0]), "=r"(r[1]), "=r"(r[2]), "=r"(r[3]) : "r"(saddr));
}

__device__ __forceinline__ void ldm_x4_t(uint32_t* r, uint32_t saddr) {
    asm volatile(
        "ldmatrix.sync.aligned.m8n8.x4.trans.shared.b16 {%0,%1,%2,%3}, [%4];"
        : "=r"(r[0]), "=r"(r[1]), "=r"(r[2]), "=r"(r[3]) : "r"(saddr));
}

// ===================================================================
// fp16 tensor-core GEMM: C[M,N] = A[M,K] @ W[K,N] + bias
// 128x128 block, 8 warps (32x64 warp tile), K-chunk 32, double buffer.
// A smem [128m][32k] fp16, stride 20 words (ldmatrix conflict-free).
// W smem [32k][128n] fp16 (no transpose), stride 68 words, consumed
// via ldmatrix.trans (the verified V-path pattern from attention).
// MODE 0: row-major store.  MODE 1: scatter to (B,H,S,DK) head layout.
// ===================================================================
#define FASTR 20
#define FWSTR 68
#define FABUF (128*FASTR)        // 2560 words
#define FWBUF (32*FWSTR)         // 2176 words
#define GEMM_SMEM_BYTES ((2*FABUF + 2*FWBUF) * 4)   // 37888

template<int MODE>
__global__ __launch_bounds__(256)
void gemm_mma(const float* __restrict__ A, const float* __restrict__ W,
              const float* __restrict__ bias, float* __restrict__ C,
              int M, int N, int K)
{
    extern __shared__ uint32_t sm[];
    uint32_t* AsBuf[2] = { sm,            sm + FABUF };
    uint32_t* BsBuf[2] = { sm + 2*FABUF,  sm + 2*FABUF + FWBUF };
    uint32_t smbase = (uint32_t)__cvta_generic_to_shared(sm);
    uint32_t aOffW[2] = { 0u, (uint32_t)FABUF };
    uint32_t bOffW[2] = { 2u*FABUF, 2u*FABUF + FWBUF };

    int tid = threadIdx.x, lane = tid & 31, wid = tid >> 5;
    int bm = blockIdx.y * 128, bn = blockIdx.x * 128;
    int wM = (wid >> 1) * 32, wN = (wid & 1) * 64;
    int g = lane >> 2, c = lane & 3;

    float acc[2][8][4];
#pragma unroll
    for (int mf = 0; mf < 2; mf++)
#pragma unroll
        for (int nf = 0; nf < 8; nf++)
#pragma unroll
            for (int r = 0; r < 4; r++) acc[mf][nf][r] = 0.f;

    const int NC = K / 32;
    int aM = tid >> 3, aK4 = tid & 7;     // A: rows 0-31 (+it*32), col4 0-7
    int bK = tid >> 5, bN4 = tid & 31;    // W: k-rows 0-7 (+it*8), n4 0-31
    float4 aR[4], bR[4];

    // ldmatrix per-lane address components
    int ldrow = (lane & 7) + 8 * ((lane >> 3) & 1);
    int ahalf = 4 * (lane >> 4);              // word offset (8 fp16)
    // A: row = wM + mf*16 + ldrow, word = ahalf + ks*8
    // B: row = ldrow + ks*16, word = wN/2 + nfp*8 + ahalf

    // ---- stage chunk 0 ----
#pragma unroll
    for (int it = 0; it < 4; it++) {
        aR[it] = *(const float4*)(A + (size_t)(bm + aM + it*32) * K + aK4 * 4);
        bR[it] = *(const float4*)(W + (size_t)(bK + it*8) * N + bn + bN4 * 4);
    }
#pragma unroll
    for (int it = 0; it < 4; it++) {
        uint2 ha = { pack_h2(aR[it].x, aR[it].y), pack_h2(aR[it].z, aR[it].w) };
        *(uint2*)(AsBuf[0] + (aM + it*32) * FASTR + aK4 * 2) = ha;
        uint2 hb = { pack_h2(bR[it].x, bR[it].y), pack_h2(bR[it].z, bR[it].w) };
        *(uint2*)(BsBuf[0] + (bK + it*8) * FWSTR + bN4 * 2) = hb;
    }
    __syncthreads();

    for (int i = 0; i < NC; i++) {
        int buf = i & 1;
        if (i + 1 < NC) {
#pragma unroll
            for (int it = 0; it < 4; it++) {
                aR[it] = *(const float4*)(A + (size_t)(bm + aM + it*32) * K
                                          + (i+1) * 32 + aK4 * 4);
                bR[it] = *(const float4*)(W + (size_t)((i+1) * 32 + bK + it*8) * N
                                          + bn + bN4 * 4);
            }
        }

        uint32_t aBase = smbase + (aOffW[buf] + (wM + ldrow) * FASTR + ahalf) * 4;
        uint32_t bBase = smbase + (bOffW[buf] + ldrow * FWSTR + wN/2 + ahalf) * 4;
#pragma unroll
        for (int ks = 0; ks < 2; ks++) {
            uint32_t af[2][4];
            ldm_x4(af[0], aBase + ks * 32);
            ldm_x4(af[1], aBase + 16 * FASTR * 4 + ks * 32);
#pragma unroll
            for (int nfp = 0; nfp < 4; nfp++) {
                uint32_t bf[4];
                ldm_x4_t(bf, bBase + ks * (16 * FWSTR * 4) + nfp * 32);
                mma_f16(acc[0][2*nfp    ], af[0], bf + 0);
                mma_f16(acc[0][2*nfp + 1], af[0], bf + 2);
                mma_f16(acc[1][2*nfp    ], af[1], bf + 0);
                mma_f16(acc[1][2*nfp + 1], af[1], bf + 2);
            }
        }

        if (i + 1 < NC) {
            __syncthreads();
            int nb = buf ^ 1;
#pragma unroll
            for (int it = 0; it < 4; it++) {
                uint2 ha = { pack_h2(aR[it].x, aR[it].y),
                             pack_h2(aR[it].z, aR[it].w) };
                *(uint2*)(AsBuf[nb] + (aM + it*32) * FASTR + aK4 * 2) = ha;
                uint2 hb = { pack_h2(bR[it].x, bR[it].y),
                             pack_h2(bR[it].z, bR[it].w) };
                *(uint2*)(BsBuf[nb] + (bK + it*8) * FWSTR + bN4 * 2) = hb;
            }
            __syncthreads();
        }
    }

    // ---- epilogue: acc frags + bias -> C (R3-verified mapping) ----
#pragma unroll
    for (int nf = 0; nf < 8; nf++) {
        int col = bn + wN + nf * 8 + 2 * c;
        float b0 = bias[col], b1 = bias[col + 1];
#pragma unroll
        for (int mf = 0; mf < 2; mf++) {
            int row = bm + wM + mf * 16 + g;
#pragma unroll
            for (int half = 0; half < 2; half++) {
                int r = row + half * 8;
                float2 w;
                w.x = acc[mf][nf][half * 2 + 0] + b0;
                w.y = acc[mf][nf][half * 2 + 1] + b1;
                float* dst;
                if (MODE == 0) {
                    dst = C + (size_t)r * N + col;
                } else {
                    int bI = r >> 11, sI = r & 2047;
                    int hI = col >> 6, dI = col & 63;
                    dst = C + (((size_t)(bI * HH + hI) * SS + sI) * DKK + dI);
                }
                *(float2*)dst = w;
            }
        }
    }
}

// ===================================================================
// Tensor-core flash attention v4 — fp16 m16n8k16 + ldmatrix (R7, best)
// ===================================================================
#define HSTR 36
#define HOFF_K   (128*HSTR)               // 4608
#define HOFF_V   (HOFF_K + 64*HSTR)       // 6912
#define HOFF_MSK (HOFF_V + 64*HSTR)       // 9216
#define ATTN_SMEM_BYTES ((HOFF_MSK + 64) * 4)   // 37120

__global__ __launch_bounds__(256, 2)
void attn_mma(const float* __restrict__ qh, const float* __restrict__ kh,
              const float* __restrict__ vh, const int* __restrict__ mask,
              float* __restrict__ scores, float* __restrict__ concat)
{
    extern __shared__ uint32_t sm[];
    uint32_t* Qs = sm;
    uint32_t* Ks = sm + HOFF_K;
    uint32_t* Vs = sm + HOFF_V;
    int*      Mk = (int*)(sm + HOFF_MSK);

    int tid = threadIdx.x, lane = tid & 31, wid = tid >> 5;
    int g = lane >> 2, c = lane & 3;
    int q0 = blockIdx.x * 128;
    int h = blockIdx.y, b = blockIdx.z;
    int wq = wid * 16;

    const float* Qb = qh + (size_t)(b * HH + h) * SS * DKK;
    const float* Kb = kh + (size_t)(b * HH + h) * SS * DKK;
    const float* Vb = vh + (size_t)(b * HH + h) * SS * DKK;
    float* scb = scores + ((size_t)(b * HH + h) * SS + q0) * SS;

    // ---- load Q tile [128][64] -> smem fp16x2 ----
#pragma unroll
    for (int i = 0; i < 8; i++) {
        int idx = tid + i * 256;
        int row = idx >> 4, c4 = idx & 15;
        float4 v = *(const float4*)(Qb + (size_t)(q0 + row) * DKK + c4 * 4);
        uint2 hh = { pack_h2(v.x, v.y), pack_h2(v.z, v.w) };
        *(uint2*)(Qs + row * HSTR + c4 * 2) = hh;
    }

    int qrow  = wq + (lane & 7) + 8 * ((lane >> 3) & 1);
    int qcsel = 4 * (lane >> 4);
    uint32_t qaddr = (uint32_t)__cvta_generic_to_shared(Qs + qrow * HSTR + qcsel);

    int krowoff = (lane & 7) + 8 * (lane >> 4);
    int kwsel   = 4 * ((lane >> 3) & 1);
    uint32_t kaddr0 = (uint32_t)__cvta_generic_to_shared(Ks + krowoff * HSTR + kwsel);

    int vrowoff = (lane & 7) + 8 * ((lane >> 3) & 1);
    int vwsel   = 4 * (lane >> 4);
    uint32_t vaddr0 = (uint32_t)__cvta_generic_to_shared(Vs + vrowoff * HSTR + vwsel);

    float m0 = -INFINITY, m1 = -INFINITY, l0 = 0.f, l1 = 0.f;
    float o[8][4];
#pragma unroll
    for (int nf = 0; nf < 8; nf++)
#pragma unroll
        for (int r = 0; r < 4; r++) o[nf][r] = 0.f;

    int rowA = wq + g;

    for (int kv0 = 0; kv0 < SS; kv0 += 64) {
        __syncthreads();
#pragma unroll
        for (int i = 0; i < 4; i++) {
            int idx = tid + i * 256;
            int row = idx >> 4, c4 = idx & 15;
            float4 kq = *(const float4*)(Kb + (size_t)(kv0 + row) * DKK + c4 * 4);
            uint2 hk = { pack_h2(kq.x, kq.y), pack_h2(kq.z, kq.w) };
            *(uint2*)(Ks + row * HSTR + c4 * 2) = hk;
            float4 vq = *(const float4*)(Vb + (size_t)(kv0 + row) * DKK + c4 * 4);
            uint2 hv = { pack_h2(vq.x, vq.y), pack_h2(vq.z, vq.w) };
            *(uint2*)(Vs + row * HSTR + c4 * 2) = hv;
        }
        if (tid < 64) Mk[tid] = mask[b * SS + kv0 + tid];
        __syncthreads();

        float s[8][4];
#pragma unroll
        for (int nf = 0; nf < 8; nf++)
#pragma unroll
            for (int r = 0; r < 4; r++) s[nf][r] = 0.f;

#pragma unroll
        for (int ks = 0; ks < 4; ks++) {
            uint32_t aq[4];
            ldm_x4(aq, qaddr + ks * 32);
#pragma unroll
            for (int nfp = 0; nfp < 4; nfp++) {
                uint32_t kb[4];
                ldm_x4(kb, kaddr0 + nfp * (16 * HSTR * 4) + ks * 32);
                mma_f16(s[2*nfp    ], aq, kb + 0);
                mma_f16(s[2*nfp + 1], aq, kb + 2);
            }
        }

        float mx0 = -INFINITY, mx1 = -INFINITY;
#pragma unroll
        for (int nf = 0; nf < 8; nf++) {
            int col = nf * 8 + 2 * c;
            int2 mv = *(const int2*)(Mk + col);
            s[nf][0] = mv.x ? s[nf][0] * 0.125f : -1e9f;
            s[nf][1] = mv.y ? s[nf][1] * 0.125f : -1e9f;
            s[nf][2] = mv.x ? s[nf][2] * 0.125f : -1e9f;
            s[nf][3] = mv.y ? s[nf][3] * 0.125f : -1e9f;
            float2 w0 = { s[nf][0], s[nf][1] };
            float2 w1 = { s[nf][2], s[nf][3] };
            *(float2*)(scb + (size_t)(rowA    ) * SS + kv0 + col) = w0;
            *(float2*)(scb + (size_t)(rowA + 8) * SS + kv0 + col) = w1;
            mx0 = fmaxf(mx0, fmaxf(s[nf][0], s[nf][1]));
            mx1 = fmaxf(mx1, fmaxf(s[nf][2], s[nf][3]));
        }
        mx0 = fmaxf(mx0, __shfl_xor_sync(0xFFFFFFFFu, mx0, 1));
        mx0 = fmaxf(mx0, __shfl_xor_sync(0xFFFFFFFFu, mx0, 2));
        mx1 = fmaxf(mx1, __shfl_xor_sync(0xFFFFFFFFu, mx1, 1));
        mx1 = fmaxf(mx1, __shfl_xor_sync(0xFFFFFFFFu, mx1, 2));

        float mn0 = fmaxf(m0, mx0), mn1 = fmaxf(m1, mx1);
        float a0 = __expf(m0 - mn0), a1 = __expf(m1 - mn1);
        m0 = mn0; m1 = mn1;

        float sum0 = 0.f, sum1 = 0.f;
#pragma unroll
        for (int nf = 0; nf < 8; nf++) {
            s[nf][0] = __expf(s[nf][0] - mn0);
            s[nf][1] = __expf(s[nf][1] - mn0);
            s[nf][2] = __expf(s[nf][2] - mn1);
            s[nf][3] = __expf(s[nf][3] - mn1);
            sum0 += s[nf][0] + s[nf][1];
            sum1 += s[nf][2] + s[nf][3];
        }
        sum0 += __shfl_xor_sync(0xFFFFFFFFu, sum0, 1);
        sum0 += __shfl_xor_sync(0xFFFFFFFFu, sum0, 2);
        sum1 += __shfl_xor_sync(0xFFFFFFFFu, sum1, 1);
        sum1 += __shfl_xor_sync(0xFFFFFFFFu, sum1, 2);
        l0 = l0 * a0 + sum0;
        l1 = l1 * a1 + sum1;

#pragma unroll
        for (int nf = 0; nf < 8; nf++) {
            o[nf][0] *= a0; o[nf][1] *= a0;
            o[nf][2] *= a1; o[nf][3] *= a1;
        }

#pragma unroll
        for (int ks = 0; ks < 4; ks++) {
            uint32_t ap[4];
            ap[0] = pack_h2(s[2*ks    ][0], s[2*ks    ][1]);
            ap[1] = pack_h2(s[2*ks    ][2], s[2*ks    ][3]);
            ap[2] = pack_h2(s[2*ks + 1][0], s[2*ks + 1][1]);
            ap[3] = pack_h2(s[2*ks + 1][2], s[2*ks + 1][3]);
#pragma unroll
            for (int nfp = 0; nfp < 4; nfp++) {
                uint32_t vb[4];
                ldm_x4_t(vb, vaddr0 + ks * (16 * HSTR * 4) + nfp * 32);
                mma_f16(o[2*nfp    ], ap, vb + 0);
                mma_f16(o[2*nfp + 1], ap, vb + 2);
            }
        }
    }

    float inv0 = 1.f / l0, inv1 = 1.f / l1;
#pragma unroll
    for (int nf = 0; nf < 8; nf++) {
        int d = nf * 8 + 2 * c;
        float2 w0 = { o[nf][0] * inv0, o[nf][1] * inv0 };
        float2 w1 = { o[nf][2] * inv1, o[nf][3] * inv1 };
        *(float2*)(concat + (size_t)(b * SS + q0 + rowA    ) * HD + h * DKK + d) = w0;
        *(float2*)(concat + (size_t)(b * SS + q0 + rowA + 8) * HD + h * DKK + d) = w1;
    }
}

// ===================================================================
extern "C" void kernel_launch(void* const* d_in, const int* in_sizes, int n_in,
                              void* d_out, int out_size)
{
    const float* q   = (const float*)d_in[0];
    const float* k   = (const float*)d_in[1];
    const float* v   = (const float*)d_in[2];
    const int*   msk = (const int*)  d_in[3];
    const float* Wq  = (const float*)d_in[4];
    const float* bq  = (const float*)d_in[5];
    const float* Wk  = (const float*)d_in[6];
    const float* bk  = (const float*)d_in[7];
    const float* Wv  = (const float*)d_in[8];
    const float* bv  = (const float*)d_in[9];
    const float* Wo  = (const float*)d_in[10];
    const float* bo  = (const float*)d_in[11];

    float* out    = (float*)d_out;              // (B,S,E)
    float* scores = out + (size_t)BB * SS * EE; // (B,H,S,S)

    float *p_qh, *p_kh, *p_vh, *p_cc;
    cudaGetSymbolAddress((void**)&p_qh, g_qh);
    cudaGetSymbolAddress((void**)&p_kh, g_kh);
    cudaGetSymbolAddress((void**)&p_vh, g_vh);
    cudaGetSymbolAddress((void**)&p_cc, g_concat);

    cudaFuncSetAttribute(gemm_mma<0>, cudaFuncAttributeMaxDynamicSharedMemorySize,
                         GEMM_SMEM_BYTES);
    cudaFuncSetAttribute(gemm_mma<1>, cudaFuncAttributeMaxDynamicSharedMemorySize,
                         GEMM_SMEM_BYTES);
    cudaFuncSetAttribute(attn_mma, cudaFuncAttributeMaxDynamicSharedMemorySize,
                         ATTN_SMEM_BYTES);

    dim3 gProj(HD / 128, (BB * SS) / 128);  // (8, 32)
    gemm_mma<1><<<gProj, 256, GEMM_SMEM_BYTES>>>(q, Wq, bq, p_qh, BB * SS, HD, EE);
    gemm_mma<1><<<gProj, 256, GEMM_SMEM_BYTES>>>(k, Wk, bk, p_kh, BB * SS, HD, EE);
    gemm_mma<1><<<gProj, 256, GEMM_SMEM_BYTES>>>(v, Wv, bv, p_vh, BB * SS, HD, EE);

    dim3 gAttn(SS / 128, HH, BB);           // (16, 16, 2)
    attn_mma<<<gAttn, 256, ATTN_SMEM_BYTES>>>(p_qh, p_kh, p_vh, msk, scores, p_cc);

    dim3 gOut(EE / 128, (BB * SS) / 128);   // (8, 32)
    gemm_mma<0><<<gOut, 256, GEMM_SMEM_BYTES>>>(p_cc, Wo, bo, out, BB * SS, EE, HD);
}

// round 9
// speedup vs baseline: 2.0016x; 1.1177x over previous
#include <cuda_runtime.h>
#include <math.h>
#include <stdint.h>

#define BB 2
#define SS 2048
#define EE 1024
#define HH 16
#define DKK 64
#define HD (HH*DKK)   // 1024

// -------- scratch (allocation-free rule: __device__ globals) --------
// Q/K/V head-layout tensors stored as packed fp16x2 (32 words per row of 64)
__device__ uint32_t g_qh16[BB*HH*SS*DKK/2];
__device__ uint32_t g_kh16[BB*HH*SS*DKK/2];
__device__ uint32_t g_vh16[BB*HH*SS*DKK/2];
__device__ float    g_concat[BB*SS*HD];   // (B*S, H*DK) fp32

// ===================================================================
// mma helpers (baseline PTX, works on compute_103)
// ===================================================================
__device__ __forceinline__ void mma_f16(float* d, const uint32_t* a,
                                        const uint32_t* b) {
    asm volatile(
        "mma.sync.aligned.m16n8k16.row.col.f32.f16.f16.f32 "
        "{%0,%1,%2,%3}, {%4,%5,%6,%7}, {%8,%9}, {%0,%1,%2,%3};"
        : "+f"(d[0]), "+f"(d[1]), "+f"(d[2]), "+f"(d[3])
        : "r"(a[0]), "r"(a[1]), "r"(a[2]), "r"(a[3]),
          "r"(b[0]), "r"(b[1]));
}

__device__ __forceinline__ uint32_t pack_h2(float lo, float hi) {
    uint32_t r;
    asm("cvt.rn.f16x2.f32 %0, %1, %2;" : "=r"(r) : "f"(hi), "f"(lo));
    return r;
}

__device__ __forceinline__ void ldm_x4(uint32_t* r, uint32_t saddr) {
    asm volatile(
        "ldmatrix.sync.aligned.m8n8.x4.shared.b16 {%0,%1,%2,%3}, [%4];"
        : "=r"(r[0]), "=r"(r[1]), "=r"(r[2]), "=r"(r[3]) : "r"(saddr));
}

__device__ __forceinline__ void ldm_x4_t(uint32_t* r, uint32_t saddr) {
    asm volatile(
        "ldmatrix.sync.aligned.m8n8.x4.trans.shared.b16 {%0,%1,%2,%3}, [%4];"
        : "=r"(r[0]), "=r"(r[1]), "=r"(r[2]), "=r"(r[3]) : "r"(saddr));
}

__device__ __forceinline__ void cp_async16(uint32_t saddr, const void* gaddr) {
    asm volatile("cp.async.cg.shared.global [%0], [%1], 16;"
                 :: "r"(saddr), "l"(gaddr));
}
#define CP_COMMIT() asm volatile("cp.async.commit_group;" ::: "memory")
#define CP_WAIT0()  asm volatile("cp.async.wait_group 0;" ::: "memory")

// ===================================================================
// fp16 tensor-core GEMM (R8-verified).  MODE 0: fp32 row-major store.
// MODE 1: packed fp16x2 scatter to (B,H,S,DK) head layout.
// ===================================================================
#define FASTR 20
#define FWSTR 68
#define FABUF (128*FASTR)
#define FWBUF (32*FWSTR)
#define GEMM_SMEM_BYTES ((2*FABUF + 2*FWBUF) * 4)   // 37888

template<int MODE>
__global__ __launch_bounds__(256)
void gemm_mma(const float* __restrict__ A, const float* __restrict__ W,
              const float* __restrict__ bias, float* __restrict__ C,
              int M, int N, int K)
{
    extern __shared__ uint32_t sm[];
    uint32_t* AsBuf[2] = { sm,            sm + FABUF };
    uint32_t* BsBuf[2] = { sm + 2*FABUF,  sm + 2*FABUF + FWBUF };
    uint32_t smbase = (uint32_t)__cvta_generic_to_shared(sm);
    uint32_t aOffW[2] = { 0u, (uint32_t)FABUF };
    uint32_t bOffW[2] = { 2u*FABUF, 2u*FABUF + FWBUF };

    int tid = threadIdx.x, lane = tid & 31, wid = tid >> 5;
    int bm = blockIdx.y * 128, bn = blockIdx.x * 128;
    int wM = (wid >> 1) * 32, wN = (wid & 1) * 64;
    int g = lane >> 2, c = lane & 3;

    float acc[2][8][4];
#pragma unroll
    for (int mf = 0; mf < 2; mf++)
#pragma unroll
        for (int nf = 0; nf < 8; nf++)
#pragma unroll
            for (int r = 0; r < 4; r++) acc[mf][nf][r] = 0.f;

    const int NC = K / 32;
    int aM = tid >> 3, aK4 = tid & 7;
    int bK = tid >> 5, bN4 = tid & 31;
    float4 aR[4], bR[4];

    int ldrow = (lane & 7) + 8 * ((lane >> 3) & 1);
    int ahalf = 4 * (lane >> 4);

#pragma unroll
    for (int it = 0; it < 4; it++) {
        aR[it] = *(const float4*)(A + (size_t)(bm + aM + it*32) * K + aK4 * 4);
        bR[it] = *(const float4*)(W + (size_t)(bK + it*8) * N + bn + bN4 * 4);
    }
#pragma unroll
    for (int it = 0; it < 4; it++) {
        uint2 ha = { pack_h2(aR[it].x, aR[it].y), pack_h2(aR[it].z, aR[it].w) };
        *(uint2*)(AsBuf[0] + (aM + it*32) * FASTR + aK4 * 2) = ha;
        uint2 hb = { pack_h2(bR[it].x, bR[it].y), pack_h2(bR[it].z, bR[it].w) };
        *(uint2*)(BsBuf[0] + (bK + it*8) * FWSTR + bN4 * 2) = hb;
    }
    __syncthreads();

    for (int i = 0; i < NC; i++) {
        int buf = i & 1;
        if (i + 1 < NC) {
#pragma unroll
            for (int it = 0; it < 4; it++) {
                aR[it] = *(const float4*)(A + (size_t)(bm + aM + it*32) * K
                                          + (i+1) * 32 + aK4 * 4);
                bR[it] = *(const float4*)(W + (size_t)((i+1) * 32 + bK + it*8) * N
                                          + bn + bN4 * 4);
            }
        }

        uint32_t aBase = smbase + (aOffW[buf] + (wM + ldrow) * FASTR + ahalf) * 4;
        uint32_t bBase = smbase + (bOffW[buf] + ldrow * FWSTR + wN/2 + ahalf) * 4;
#pragma unroll
        for (int ks = 0; ks < 2; ks++) {
            uint32_t af[2][4];
            ldm_x4(af[0], aBase + ks * 32);
            ldm_x4(af[1], aBase + 16 * FASTR * 4 + ks * 32);
#pragma unroll
            for (int nfp = 0; nfp < 4; nfp++) {
                uint32_t bf[4];
                ldm_x4_t(bf, bBase + ks * (16 * FWSTR * 4) + nfp * 32);
                mma_f16(acc[0][2*nfp    ], af[0], bf + 0);
                mma_f16(acc[0][2*nfp + 1], af[0], bf + 2);
                mma_f16(acc[1][2*nfp    ], af[1], bf + 0);
                mma_f16(acc[1][2*nfp + 1], af[1], bf + 2);
            }
        }

        if (i + 1 < NC) {
            __syncthreads();
            int nb = buf ^ 1;
#pragma unroll
            for (int it = 0; it < 4; it++) {
                uint2 ha = { pack_h2(aR[it].x, aR[it].y),
                             pack_h2(aR[it].z, aR[it].w) };
                *(uint2*)(AsBuf[nb] + (aM + it*32) * FASTR + aK4 * 2) = ha;
                uint2 hb = { pack_h2(bR[it].x, bR[it].y),
                             pack_h2(bR[it].z, bR[it].w) };
                *(uint2*)(BsBuf[nb] + (bK + it*8) * FWSTR + bN4 * 2) = hb;
            }
            __syncthreads();
        }
    }

#pragma unroll
    for (int nf = 0; nf < 8; nf++) {
        int col = bn + wN + nf * 8 + 2 * c;
        float b0 = bias[col], b1 = bias[col + 1];
#pragma unroll
        for (int mf = 0; mf < 2; mf++) {
            int row = bm + wM + mf * 16 + g;
#pragma unroll
            for (int half = 0; half < 2; half++) {
                int r = row + half * 8;
                float wx = acc[mf][nf][half * 2 + 0] + b0;
                float wy = acc[mf][nf][half * 2 + 1] + b1;
                if (MODE == 0) {
                    float2 w = { wx, wy };
                    *(float2*)(C + (size_t)r * N + col) = w;
                } else {
                    int bI = r >> 11, sI = r & 2047;
                    int hI = col >> 6, dI = col & 63;
                    uint32_t* dst = (uint32_t*)C +
                        (((size_t)(bI * HH + hI) * SS + sI) * (DKK/2) + (dI >> 1));
                    *dst = pack_h2(wx, wy);
                }
            }
        }
    }
}

// ===================================================================
// Tensor-core flash attention v5 — fp16 in gmem + cp.async K/V pipeline.
//  - Q/K/V read as packed fp16x2 (no cvt, half bytes).
//  - K/V double-buffered in smem, filled by cp.async.cg overlapping
//    the previous tile's full compute.  Mask double-buffered too.
// ===================================================================
#define HSTR 36
#define KOFF  (128*HSTR)             // 4608
#define KVBUF (64*HSTR)              // 2304
#define VOFF  (KOFF + 2*KVBUF)       // 9216
#define MOFF  (VOFF + 2*KVBUF)       // 13824
#define ATTN_SMEM_BYTES ((MOFF + 128) * 4)   // 55808

__global__ __launch_bounds__(256, 2)
void attn_mma(const uint32_t* __restrict__ qh, const uint32_t* __restrict__ kh,
              const uint32_t* __restrict__ vh, const int* __restrict__ mask,
              float* __restrict__ scores, float* __restrict__ concat)
{
    extern __shared__ uint32_t sm[];
    uint32_t* Qs = sm;
    int*      Mk = (int*)(sm + MOFF);
    uint32_t smbase = (uint32_t)__cvta_generic_to_shared(sm);

    int tid = threadIdx.x, lane = tid & 31, wid = tid >> 5;
    int g = lane >> 2, c = lane & 3;
    int q0 = blockIdx.x * 128;
    int h = blockIdx.y, b = blockIdx.z;
    int wq = wid * 16;

    const uint4* Qg4 = (const uint4*)(qh + (size_t)(b * HH + h) * SS * 32) + (size_t)q0 * 8;
    const uint4* Kg4 = (const uint4*)(kh + (size_t)(b * HH + h) * SS * 32);
    const uint4* Vg4 = (const uint4*)(vh + (size_t)(b * HH + h) * SS * 32);
    float* scb = scores + ((size_t)(b * HH + h) * SS + q0) * SS;

    // ---- load Q tile [128 rows][32 words] -> smem (direct fp16) ----
#pragma unroll
    for (int i = 0; i < 4; i++) {
        int idx = tid + i * 256;
        int row = idx >> 3, w4 = idx & 7;
        *(uint4*)(Qs + row * HSTR + w4 * 4) = Qg4[row * 8 + w4];
    }

    // per-thread cp.async coordinates (2 x uint4 per tensor)
    int cprow[2], cpw4[2];
#pragma unroll
    for (int i = 0; i < 2; i++) {
        int idx = tid + i * 256;
        cprow[i] = idx >> 3; cpw4[i] = idx & 7;
    }

    // ---- prologue: tile 0 cp.async + mask prefetch ----
#pragma unroll
    for (int i = 0; i < 2; i++) {
        uint32_t ks_ = smbase + (KOFF + cprow[i] * HSTR + cpw4[i] * 4) * 4;
        cp_async16(ks_, Kg4 + cprow[i] * 8 + cpw4[i]);
        uint32_t vs_ = smbase + (VOFF + cprow[i] * HSTR + cpw4[i] * 4) * 4;
        cp_async16(vs_, Vg4 + cprow[i] * 8 + cpw4[i]);
    }
    CP_COMMIT();
    int mkR = (tid < 64) ? mask[b * SS + tid] : 0;

    // ldmatrix lane addresses
    int qrow  = wq + (lane & 7) + 8 * ((lane >> 3) & 1);
    int qcsel = 4 * (lane >> 4);
    uint32_t qaddr = smbase + (qrow * HSTR + qcsel) * 4;

    int krowoff = (lane & 7) + 8 * (lane >> 4);
    int kwsel   = 4 * ((lane >> 3) & 1);
    uint32_t kLane = (uint32_t)(krowoff * HSTR + kwsel) * 4;

    int vrowoff = (lane & 7) + 8 * ((lane >> 3) & 1);
    int vwsel   = 4 * (lane >> 4);
    uint32_t vLane = (uint32_t)(vrowoff * HSTR + vwsel) * 4;

    float m0 = -INFINITY, m1 = -INFINITY, l0 = 0.f, l1 = 0.f;
    float o[8][4];
#pragma unroll
    for (int nf = 0; nf < 8; nf++)
#pragma unroll
        for (int r = 0; r < 4; r++) o[nf][r] = 0.f;

    int rowA = wq + g;

    for (int it = 0; it < SS / 64; it++) {
        int buf = it & 1;
        int kv0 = it * 64;
        CP_WAIT0();                       // tile it resident in buf
        if (tid < 64) Mk[buf * 64 + tid] = mkR;
        __syncthreads();                  // data+mask visible; prev readers of buf^1 done

        // ---- issue next tile into buf^1 (overlaps all compute below) ----
        if (it + 1 < SS / 64) {
            int nbase = (it + 1) * 64;
#pragma unroll
            for (int i = 0; i < 2; i++) {
                uint32_t ks_ = smbase + (KOFF + (buf ^ 1) * KVBUF
                                         + cprow[i] * HSTR + cpw4[i] * 4) * 4;
                cp_async16(ks_, Kg4 + (nbase + cprow[i]) * 8 + cpw4[i]);
                uint32_t vs_ = smbase + (VOFF + (buf ^ 1) * KVBUF
                                         + cprow[i] * HSTR + cpw4[i] * 4) * 4;
                cp_async16(vs_, Vg4 + (nbase + cprow[i]) * 8 + cpw4[i]);
            }
            CP_COMMIT();
            mkR = (tid < 64) ? mask[b * SS + nbase + tid] : 0;
        }

        uint32_t kaddr0 = smbase + (KOFF + buf * KVBUF) * 4 + kLane;
        uint32_t vaddr0 = smbase + (VOFF + buf * KVBUF) * 4 + vLane;
        const int* MkB = Mk + buf * 64;

        // ---- S = Q @ K^T ----
        float s[8][4];
#pragma unroll
        for (int nf = 0; nf < 8; nf++)
#pragma unroll
            for (int r = 0; r < 4; r++) s[nf][r] = 0.f;

#pragma unroll
        for (int ks = 0; ks < 4; ks++) {
            uint32_t aq[4];
            ldm_x4(aq, qaddr + ks * 32);
#pragma unroll
            for (int nfp = 0; nfp < 4; nfp++) {
                uint32_t kb[4];
                ldm_x4(kb, kaddr0 + nfp * (16 * HSTR * 4) + ks * 32);
                mma_f16(s[2*nfp    ], aq, kb + 0);
                mma_f16(s[2*nfp + 1], aq, kb + 2);
            }
        }

        // ---- mask + scale + write scores + row max ----
        float mx0 = -INFINITY, mx1 = -INFINITY;
#pragma unroll
        for (int nf = 0; nf < 8; nf++) {
            int col = nf * 8 + 2 * c;
            int2 mv = *(const int2*)(MkB + col);
            s[nf][0] = mv.x ? s[nf][0] * 0.125f : -1e9f;
            s[nf][1] = mv.y ? s[nf][1] * 0.125f : -1e9f;
            s[nf][2] = mv.x ? s[nf][2] * 0.125f : -1e9f;
            s[nf][3] = mv.y ? s[nf][3] * 0.125f : -1e9f;
            float2 w0 = { s[nf][0], s[nf][1] };
            float2 w1 = { s[nf][2], s[nf][3] };
            *(float2*)(scb + (size_t)(rowA    ) * SS + kv0 + col) = w0;
            *(float2*)(scb + (size_t)(rowA + 8) * SS + kv0 + col) = w1;
            mx0 = fmaxf(mx0, fmaxf(s[nf][0], s[nf][1]));
            mx1 = fmaxf(mx1, fmaxf(s[nf][2], s[nf][3]));
        }
        mx0 = fmaxf(mx0, __shfl_xor_sync(0xFFFFFFFFu, mx0, 1));
        mx0 = fmaxf(mx0, __shfl_xor_sync(0xFFFFFFFFu, mx0, 2));
        mx1 = fmaxf(mx1, __shfl_xor_sync(0xFFFFFFFFu, mx1, 1));
        mx1 = fmaxf(mx1, __shfl_xor_sync(0xFFFFFFFFu, mx1, 2));

        float mn0 = fmaxf(m0, mx0), mn1 = fmaxf(m1, mx1);
        float a0 = __expf(m0 - mn0), a1 = __expf(m1 - mn1);
        m0 = mn0; m1 = mn1;

        float sum0 = 0.f, sum1 = 0.f;
#pragma unroll
        for (int nf = 0; nf < 8; nf++) {
            s[nf][0] = __expf(s[nf][0] - mn0);
            s[nf][1] = __expf(s[nf][1] - mn0);
            s[nf][2] = __expf(s[nf][2] - mn1);
            s[nf][3] = __expf(s[nf][3] - mn1);
            sum0 += s[nf][0] + s[nf][1];
            sum1 += s[nf][2] + s[nf][3];
        }
        sum0 += __shfl_xor_sync(0xFFFFFFFFu, sum0, 1);
        sum0 += __shfl_xor_sync(0xFFFFFFFFu, sum0, 2);
        sum1 += __shfl_xor_sync(0xFFFFFFFFu, sum1, 1);
        sum1 += __shfl_xor_sync(0xFFFFFFFFu, sum1, 2);
        l0 = l0 * a0 + sum0;
        l1 = l1 * a1 + sum1;

#pragma unroll
        for (int nf = 0; nf < 8; nf++) {
            o[nf][0] *= a0; o[nf][1] *= a0;
            o[nf][2] *= a1; o[nf][3] *= a1;
        }

        // ---- O += P @ V : A-frags straight from accumulators ----
#pragma unroll
        for (int ks = 0; ks < 4; ks++) {
            uint32_t ap[4];
            ap[0] = pack_h2(s[2*ks    ][0], s[2*ks    ][1]);
            ap[1] = pack_h2(s[2*ks    ][2], s[2*ks    ][3]);
            ap[2] = pack_h2(s[2*ks + 1][0], s[2*ks + 1][1]);
            ap[3] = pack_h2(s[2*ks + 1][2], s[2*ks + 1][3]);
#pragma unroll
            for (int nfp = 0; nfp < 4; nfp++) {
                uint32_t vb[4];
                ldm_x4_t(vb, vaddr0 + ks * (16 * HSTR * 4) + nfp * 32);
                mma_f16(o[2*nfp    ], ap, vb + 0);
                mma_f16(o[2*nfp + 1], ap, vb + 2);
            }
        }
    }

    float inv0 = 1.f / l0, inv1 = 1.f / l1;
#pragma unroll
    for (int nf = 0; nf < 8; nf++) {
        int d = nf * 8 + 2 * c;
        float2 w0 = { o[nf][0] * inv0, o[nf][1] * inv0 };
        float2 w1 = { o[nf][2] * inv1, o[nf][3] * inv1 };
        *(float2*)(concat + (size_t)(b * SS + q0 + rowA    ) * HD + h * DKK + d) = w0;
        *(float2*)(concat + (size_t)(b * SS + q0 + rowA + 8) * HD + h * DKK + d) = w1;
    }
}

// ===================================================================
extern "C" void kernel_launch(void* const* d_in, const int* in_sizes, int n_in,
                              void* d_out, int out_size)
{
    const float* q   = (const float*)d_in[0];
    const float* k   = (const float*)d_in[1];
    const float* v   = (const float*)d_in[2];
    const int*   msk = (const int*)  d_in[3];
    const float* Wq  = (const float*)d_in[4];
    const float* bq  = (const float*)d_in[5];
    const float* Wk  = (const float*)d_in[6];
    const float* bk  = (const float*)d_in[7];
    const float* Wv  = (const float*)d_in[8];
    const float* bv  = (const float*)d_in[9];
    const float* Wo  = (const float*)d_in[10];
    const float* bo  = (const float*)d_in[11];

    float* out    = (float*)d_out;              // (B,S,E)
    float* scores = out + (size_t)BB * SS * EE; // (B,H,S,S)

    uint32_t *p_qh, *p_kh, *p_vh;
    float *p_cc;
    cudaGetSymbolAddress((void**)&p_qh, g_qh16);
    cudaGetSymbolAddress((void**)&p_kh, g_kh16);
    cudaGetSymbolAddress((void**)&p_vh, g_vh16);
    cudaGetSymbolAddress((void**)&p_cc, g_concat);

    cudaFuncSetAttribute(gemm_mma<0>, cudaFuncAttributeMaxDynamicSharedMemorySize,
                         GEMM_SMEM_BYTES);
    cudaFuncSetAttribute(gemm_mma<1>, cudaFuncAttributeMaxDynamicSharedMemorySize,
                         GEMM_SMEM_BYTES);
    cudaFuncSetAttribute(attn_mma, cudaFuncAttributeMaxDynamicSharedMemorySize,
                         ATTN_SMEM_BYTES);

    dim3 gProj(HD / 128, (BB * SS) / 128);  // (8, 32)
    gemm_mma<1><<<gProj, 256, GEMM_SMEM_BYTES>>>(q, Wq, bq, (float*)p_qh, BB * SS, HD, EE);
    gemm_mma<1><<<gProj, 256, GEMM_SMEM_BYTES>>>(k, Wk, bk, (float*)p_kh, BB * SS, HD, EE);
    gemm_mma<1><<<gProj, 256, GEMM_SMEM_BYTES>>>(v, Wv, bv, (float*)p_vh, BB * SS, HD, EE);

    dim3 gAttn(SS / 128, HH, BB);           // (16, 16, 2)
    attn_mma<<<gAttn, 256, ATTN_SMEM_BYTES>>>(p_qh, p_kh, p_vh, msk, scores, p_cc);

    dim3 gOut(EE / 128, (BB * SS) / 128);   // (8, 32)
    gemm_mma<0><<<gOut, 256, GEMM_SMEM_BYTES>>>(p_cc, Wo, bo, out, BB * SS, EE, HD);
}

// round 10
// speedup vs baseline: 2.1746x; 1.0864x over previous
#include <cuda_runtime.h>
#include <math.h>
#include <stdint.h>

#define BB 2
#define SS 2048
#define EE 1024
#define HH 16
#define DKK 64
#define HD (HH*DKK)   // 1024

// -------- scratch (allocation-free rule: __device__ globals) --------
__device__ uint32_t g_qh16[BB*HH*SS*DKK/2];   // head-layout fp16x2
__device__ uint32_t g_kh16[BB*HH*SS*DKK/2];
__device__ uint32_t g_vh16[BB*HH*SS*DKK/2];
__device__ uint32_t g_x16[3][BB*SS*EE/2];     // q,k,v inputs fp16x2
__device__ uint32_t g_w16[4][EE*HD/2];        // Wq,Wk,Wv,Wo fp16x2
__device__ uint32_t g_cc16[BB*SS*HD/2];       // concat fp16x2

// ===================================================================
// helpers (baseline PTX, works on compute_103)
// ===================================================================
__device__ __forceinline__ void mma_f16(float* d, const uint32_t* a,
                                        const uint32_t* b) {
    asm volatile(
        "mma.sync.aligned.m16n8k16.row.col.f32.f16.f16.f32 "
        "{%0,%1,%2,%3}, {%4,%5,%6,%7}, {%8,%9}, {%0,%1,%2,%3};"
        : "+f"(d[0]), "+f"(d[1]), "+f"(d[2]), "+f"(d[3])
        : "r"(a[0]), "r"(a[1]), "r"(a[2]), "r"(a[3]),
          "r"(b[0]), "r"(b[1]));
}

__device__ __forceinline__ uint32_t pack_h2(float lo, float hi) {
    uint32_t r;
    asm("cvt.rn.f16x2.f32 %0, %1, %2;" : "=r"(r) : "f"(hi), "f"(lo));
    return r;
}

__device__ __forceinline__ void ldm_x4(uint32_t* r, uint32_t saddr) {
    asm volatile(
        "ldmatrix.sync.aligned.m8n8.x4.shared.b16 {%0,%1,%2,%3}, [%4];"
        : "=r"(r[0]), "=r"(r[1]), "=r"(r[2]), "=r"(r[3]) : "r"(saddr));
}

__device__ __forceinline__ void ldm_x4_t(uint32_t* r, uint32_t saddr) {
    asm volatile(
        "ldmatrix.sync.aligned.m8n8.x4.trans.shared.b16 {%0,%1,%2,%3}, [%4];"
        : "=r"(r[0]), "=r"(r[1]), "=r"(r[2]), "=r"(r[3]) : "r"(saddr));
}

__device__ __forceinline__ void cp_async16(uint32_t saddr, const void* gaddr) {
    asm volatile("cp.async.cg.shared.global [%0], [%1], 16;"
                 :: "r"(saddr), "l"(gaddr));
}
#define CP_COMMIT() asm volatile("cp.async.commit_group;" ::: "memory")
#define CP_WAIT0()  asm volatile("cp.async.wait_group 0;" ::: "memory")
#define CP_WAIT1()  asm volatile("cp.async.wait_group 1;" ::: "memory")

// ---- fp32 -> packed fp16 conversion ----
__global__ __launch_bounds__(256) void cvtk(const float4* __restrict__ in,
                                            uint2* __restrict__ out, int n4) {
    int i = blockIdx.x * blockDim.x + threadIdx.x;
    if (i < n4) {
        float4 v = in[i];
        out[i] = make_uint2(pack_h2(v.x, v.y), pack_h2(v.z, v.w));
    }
}

// ===================================================================
// fp16 tensor-core GEMM, fp16 A/W in gmem, cp.async 3-stage pipeline.
// C[M,N] = A[M,K] @ W[K,N] + bias.  128x128 block, 8 warps.
// MODE 0: fp32 row-major store.  MODE 1: fp16x2 head-layout scatter.
// ===================================================================
#define FASTR 20
#define FWSTR 68
#define FABUF (128*FASTR)        // 2560 words
#define FWBUF (32*FWSTR)         // 2176 words
#define STGW  (FABUF + FWBUF)    // 4736 words per stage
#define GEMM_SMEM_BYTES (3 * STGW * 4)   // 56832

template<int MODE>
__global__ __launch_bounds__(256)
void gemm_h(const uint32_t* __restrict__ A, const uint32_t* __restrict__ W,
            const float* __restrict__ bias, void* __restrict__ Cv,
            int M, int N, int K)
{
    extern __shared__ uint32_t sm[];
    uint32_t smbase = (uint32_t)__cvta_generic_to_shared(sm);

    int tid = threadIdx.x, lane = tid & 31, wid = tid >> 5;
    int bm = blockIdx.y * 128, bn = blockIdx.x * 128;
    int wM = (wid >> 1) * 32, wN = (wid & 1) * 64;
    int g = lane >> 2, c = lane & 3;

    float acc[2][8][4];
#pragma unroll
    for (int mf = 0; mf < 2; mf++)
#pragma unroll
        for (int nf = 0; nf < 8; nf++)
#pragma unroll
            for (int r = 0; r < 4; r++) acc[mf][nf][r] = 0.f;

    const int NC = K / 32;
    const int Kw = K / 2, Nw = N / 2;

    // cp.async coordinates: A 512 x 16B, W 512 x 16B, 2 each per thread
    int aRow[2], aW4[2], wRow[2], wW4[2];
#pragma unroll
    for (int i = 0; i < 2; i++) {
        int idx = tid + i * 256;
        aRow[i] = idx >> 2;  aW4[i] = idx & 3;
        wRow[i] = idx >> 4;  wW4[i] = idx & 15;
    }

    // ldmatrix lane addressing (R8-verified)
    int ldrow = (lane & 7) + 8 * ((lane >> 3) & 1);
    int ahalf = 4 * (lane >> 4);

    auto stage = [&](int ci, int s) {
        uint32_t aOff = smbase + (s * STGW) * 4;
        uint32_t bOff = aOff + FABUF * 4;
#pragma unroll
        for (int i = 0; i < 2; i++) {
            cp_async16(aOff + (aRow[i] * FASTR + aW4[i] * 4) * 4,
                       A + (size_t)(bm + aRow[i]) * Kw + ci * 16 + aW4[i] * 4);
            cp_async16(bOff + (wRow[i] * FWSTR + wW4[i] * 4) * 4,
                       W + (size_t)(ci * 32 + wRow[i]) * Nw + bn / 2 + wW4[i] * 4);
        }
        CP_COMMIT();
    };

    stage(0, 0);
    stage(1, 1);

    for (int i = 0; i < NC; i++) {
        int s = i % 3;
        if (i + 2 < NC) { CP_WAIT1(); } else { CP_WAIT0(); }
        __syncthreads();                 // chunk i resident; stage s+2 free
        if (i + 2 < NC) stage(i + 2, (i + 2) % 3);

        uint32_t aBase = smbase + (s * STGW + (wM + ldrow) * FASTR + ahalf) * 4;
        uint32_t bBase = smbase + (s * STGW + FABUF + ldrow * FWSTR + wN/2 + ahalf) * 4;
#pragma unroll
        for (int ks = 0; ks < 2; ks++) {
            uint32_t af[2][4];
            ldm_x4(af[0], aBase + ks * 32);
            ldm_x4(af[1], aBase + 16 * FASTR * 4 + ks * 32);
#pragma unroll
            for (int nfp = 0; nfp < 4; nfp++) {
                uint32_t bf[4];
                ldm_x4_t(bf, bBase + ks * (16 * FWSTR * 4) + nfp * 32);
                mma_f16(acc[0][2*nfp    ], af[0], bf + 0);
                mma_f16(acc[0][2*nfp + 1], af[0], bf + 2);
                mma_f16(acc[1][2*nfp    ], af[1], bf + 0);
                mma_f16(acc[1][2*nfp + 1], af[1], bf + 2);
            }
        }
        __syncthreads();                 // done reading stage s before reuse
    }

    // ---- epilogue (R3-verified frag mapping) ----
#pragma unroll
    for (int nf = 0; nf < 8; nf++) {
        int col = bn + wN + nf * 8 + 2 * c;
        float b0 = bias[col], b1 = bias[col + 1];
#pragma unroll
        for (int mf = 0; mf < 2; mf++) {
            int row = bm + wM + mf * 16 + g;
#pragma unroll
            for (int half = 0; half < 2; half++) {
                int r = row + half * 8;
                float wx = acc[mf][nf][half * 2 + 0] + b0;
                float wy = acc[mf][nf][half * 2 + 1] + b1;
                if (MODE == 0) {
                    float2 w = { wx, wy };
                    *(float2*)((float*)Cv + (size_t)r * N + col) = w;
                } else {
                    int bI = r >> 11, sI = r & 2047;
                    int hI = col >> 6, dI = col & 63;
                    uint32_t* dst = (uint32_t*)Cv +
                        (((size_t)(bI * HH + hI) * SS + sI) * (DKK/2) + (dI >> 1));
                    *dst = pack_h2(wx, wy);
                }
            }
        }
    }
}

// ===================================================================
// Tensor-core flash attention (R9-verified) — fp16 + cp.async pipeline.
// Change vs R9: concat written as packed fp16x2.
// ===================================================================
#define HSTR 36
#define KOFF  (128*HSTR)
#define KVBUF (64*HSTR)
#define VOFF  (KOFF + 2*KVBUF)
#define MOFF  (VOFF + 2*KVBUF)
#define ATTN_SMEM_BYTES ((MOFF + 128) * 4)   // 55808

__global__ __launch_bounds__(256, 2)
void attn_mma(const uint32_t* __restrict__ qh, const uint32_t* __restrict__ kh,
              const uint32_t* __restrict__ vh, const int* __restrict__ mask,
              float* __restrict__ scores, uint32_t* __restrict__ concat)
{
    extern __shared__ uint32_t sm[];
    uint32_t* Qs = sm;
    int*      Mk = (int*)(sm + MOFF);
    uint32_t smbase = (uint32_t)__cvta_generic_to_shared(sm);

    int tid = threadIdx.x, lane = tid & 31, wid = tid >> 5;
    int g = lane >> 2, c = lane & 3;
    int q0 = blockIdx.x * 128;
    int h = blockIdx.y, b = blockIdx.z;
    int wq = wid * 16;

    const uint4* Qg4 = (const uint4*)(qh + (size_t)(b * HH + h) * SS * 32) + (size_t)q0 * 8;
    const uint4* Kg4 = (const uint4*)(kh + (size_t)(b * HH + h) * SS * 32);
    const uint4* Vg4 = (const uint4*)(vh + (size_t)(b * HH + h) * SS * 32);
    float* scb = scores + ((size_t)(b * HH + h) * SS + q0) * SS;

#pragma unroll
    for (int i = 0; i < 4; i++) {
        int idx = tid + i * 256;
        int row = idx >> 3, w4 = idx & 7;
        *(uint4*)(Qs + row * HSTR + w4 * 4) = Qg4[row * 8 + w4];
    }

    int cprow[2], cpw4[2];
#pragma unroll
    for (int i = 0; i < 2; i++) {
        int idx = tid + i * 256;
        cprow[i] = idx >> 3; cpw4[i] = idx & 7;
    }

#pragma unroll
    for (int i = 0; i < 2; i++) {
        uint32_t ks_ = smbase + (KOFF + cprow[i] * HSTR + cpw4[i] * 4) * 4;
        cp_async16(ks_, Kg4 + cprow[i] * 8 + cpw4[i]);
        uint32_t vs_ = smbase + (VOFF + cprow[i] * HSTR + cpw4[i] * 4) * 4;
        cp_async16(vs_, Vg4 + cprow[i] * 8 + cpw4[i]);
    }
    CP_COMMIT();
    int mkR = (tid < 64) ? mask[b * SS + tid] : 0;

    int qrow  = wq + (lane & 7) + 8 * ((lane >> 3) & 1);
    int qcsel = 4 * (lane >> 4);
    uint32_t qaddr = smbase + (qrow * HSTR + qcsel) * 4;

    int krowoff = (lane & 7) + 8 * (lane >> 4);
    int kwsel   = 4 * ((lane >> 3) & 1);
    uint32_t kLane = (uint32_t)(krowoff * HSTR + kwsel) * 4;

    int vrowoff = (lane & 7) + 8 * ((lane >> 3) & 1);
    int vwsel   = 4 * (lane >> 4);
    uint32_t vLane = (uint32_t)(vrowoff * HSTR + vwsel) * 4;

    float m0 = -INFINITY, m1 = -INFINITY, l0 = 0.f, l1 = 0.f;
    float o[8][4];
#pragma unroll
    for (int nf = 0; nf < 8; nf++)
#pragma unroll
        for (int r = 0; r < 4; r++) o[nf][r] = 0.f;

    int rowA = wq + g;

    for (int it = 0; it < SS / 64; it++) {
        int buf = it & 1;
        int kv0 = it * 64;
        CP_WAIT0();
        if (tid < 64) Mk[buf * 64 + tid] = mkR;
        __syncthreads();

        if (it + 1 < SS / 64) {
            int nbase = (it + 1) * 64;
#pragma unroll
            for (int i = 0; i < 2; i++) {
                uint32_t ks_ = smbase + (KOFF + (buf ^ 1) * KVBUF
                                         + cprow[i] * HSTR + cpw4[i] * 4) * 4;
                cp_async16(ks_, Kg4 + (nbase + cprow[i]) * 8 + cpw4[i]);
                uint32_t vs_ = smbase + (VOFF + (buf ^ 1) * KVBUF
                                         + cprow[i] * HSTR + cpw4[i] * 4) * 4;
                cp_async16(vs_, Vg4 + (nbase + cprow[i]) * 8 + cpw4[i]);
            }
            CP_COMMIT();
            mkR = (tid < 64) ? mask[b * SS + nbase + tid] : 0;
        }

        uint32_t kaddr0 = smbase + (KOFF + buf * KVBUF) * 4 + kLane;
        uint32_t vaddr0 = smbase + (VOFF + buf * KVBUF) * 4 + vLane;
        const int* MkB = Mk + buf * 64;

        float s[8][4];
#pragma unroll
        for (int nf = 0; nf < 8; nf++)
#pragma unroll
            for (int r = 0; r < 4; r++) s[nf][r] = 0.f;

#pragma unroll
        for (int ks = 0; ks < 4; ks++) {
            uint32_t aq[4];
            ldm_x4(aq, qaddr + ks * 32);
#pragma unroll
            for (int nfp = 0; nfp < 4; nfp++) {
                uint32_t kb[4];
                ldm_x4(kb, kaddr0 + nfp * (16 * HSTR * 4) + ks * 32);
                mma_f16(s[2*nfp    ], aq, kb + 0);
                mma_f16(s[2*nfp + 1], aq, kb + 2);
            }
        }

        float mx0 = -INFINITY, mx1 = -INFINITY;
#pragma unroll
        for (int nf = 0; nf < 8; nf++) {
            int col = nf * 8 + 2 * c;
            int2 mv = *(const int2*)(MkB + col);
            s[nf][0] = mv.x ? s[nf][0] * 0.125f : -1e9f;
            s[nf][1] = mv.y ? s[nf][1] * 0.125f : -1e9f;
            s[nf][2] = mv.x ? s[nf][2] * 0.125f : -1e9f;
            s[nf][3] = mv.y ? s[nf][3] * 0.125f : -1e9f;
            float2 w0 = { s[nf][0], s[nf][1] };
            float2 w1 = { s[nf][2], s[nf][3] };
            *(float2*)(scb + (size_t)(rowA    ) * SS + kv0 + col) = w0;
            *(float2*)(scb + (size_t)(rowA + 8) * SS + kv0 + col) = w1;
            mx0 = fmaxf(mx0, fmaxf(s[nf][0], s[nf][1]));
            mx1 = fmaxf(mx1, fmaxf(s[nf][2], s[nf][3]));
        }
        mx0 = fmaxf(mx0, __shfl_xor_sync(0xFFFFFFFFu, mx0, 1));
        mx0 = fmaxf(mx0, __shfl_xor_sync(0xFFFFFFFFu, mx0, 2));
        mx1 = fmaxf(mx1, __shfl_xor_sync(0xFFFFFFFFu, mx1, 1));
        mx1 = fmaxf(mx1, __shfl_xor_sync(0xFFFFFFFFu, mx1, 2));

        float mn0 = fmaxf(m0, mx0), mn1 = fmaxf(m1, mx1);
        float a0 = __expf(m0 - mn0), a1 = __expf(m1 - mn1);
        m0 = mn0; m1 = mn1;

        float sum0 = 0.f, sum1 = 0.f;
#pragma unroll
        for (int nf = 0; nf < 8; nf++) {
            s[nf][0] = __expf(s[nf][0] - mn0);
            s[nf][1] = __expf(s[nf][1] - mn0);
            s[nf][2] = __expf(s[nf][2] - mn1);
            s[nf][3] = __expf(s[nf][3] - mn1);
            sum0 += s[nf][0] + s[nf][1];
            sum1 += s[nf][2] + s[nf][3];
        }
        sum0 += __shfl_xor_sync(0xFFFFFFFFu, sum0, 1);
        sum0 += __shfl_xor_sync(0xFFFFFFFFu, sum0, 2);
        sum1 += __shfl_xor_sync(0xFFFFFFFFu, sum1, 1);
        sum1 += __shfl_xor_sync(0xFFFFFFFFu, sum1, 2);
        l0 = l0 * a0 + sum0;
        l1 = l1 * a1 + sum1;

#pragma unroll
        for (int nf = 0; nf < 8; nf++) {
            o[nf][0] *= a0; o[nf][1] *= a0;
            o[nf][2] *= a1; o[nf][3] *= a1;
        }

#pragma unroll
        for (int ks = 0; ks < 4; ks++) {
            uint32_t ap[4];
            ap[0] = pack_h2(s[2*ks    ][0], s[2*ks    ][1]);
            ap[1] = pack_h2(s[2*ks    ][2], s[2*ks    ][3]);
            ap[2] = pack_h2(s[2*ks + 1][0], s[2*ks + 1][1]);
            ap[3] = pack_h2(s[2*ks + 1][2], s[2*ks + 1][3]);
#pragma unroll
            for (int nfp = 0; nfp < 4; nfp++) {
                uint32_t vb[4];
                ldm_x4_t(vb, vaddr0 + ks * (16 * HSTR * 4) + nfp * 32);
                mma_f16(o[2*nfp    ], ap, vb + 0);
                mma_f16(o[2*nfp + 1], ap, vb + 2);
            }
        }
    }

    // ---- finalize: /l, write concat as packed fp16 ----
    float inv0 = 1.f / l0, inv1 = 1.f / l1;
#pragma unroll
    for (int nf = 0; nf < 8; nf++) {
        int d = nf * 8 + 2 * c;
        size_t w0i = (size_t)(b * SS + q0 + rowA    ) * (HD/2) + (h * DKK + d) / 2;
        size_t w1i = (size_t)(b * SS + q0 + rowA + 8) * (HD/2) + (h * DKK + d) / 2;
        concat[w0i] = pack_h2(o[nf][0] * inv0, o[nf][1] * inv0);
        concat[w1i] = pack_h2(o[nf][2] * inv1, o[nf][3] * inv1);
    }
}

// ===================================================================
extern "C" void kernel_launch(void* const* d_in, const int* in_sizes, int n_in,
                              void* d_out, int out_size)
{
    const float* q   = (const float*)d_in[0];
    const float* k   = (const float*)d_in[1];
    const float* v   = (const float*)d_in[2];
    const int*   msk = (const int*)  d_in[3];
    const float* Wq  = (const float*)d_in[4];
    const float* bq  = (const float*)d_in[5];
    const float* Wk  = (const float*)d_in[6];
    const float* bk  = (const float*)d_in[7];
    const float* Wv  = (const float*)d_in[8];
    const float* bv  = (const float*)d_in[9];
    const float* Wo  = (const float*)d_in[10];
    const float* bo  = (const float*)d_in[11];

    float* out    = (float*)d_out;              // (B,S,E)
    float* scores = out + (size_t)BB * SS * EE; // (B,H,S,S)

    uint32_t *p_qh, *p_kh, *p_vh, *p_x, *p_w, *p_cc;
    cudaGetSymbolAddress((void**)&p_qh, g_qh16);
    cudaGetSymbolAddress((void**)&p_kh, g_kh16);
    cudaGetSymbolAddress((void**)&p_vh, g_vh16);
    cudaGetSymbolAddress((void**)&p_x,  g_x16);
    cudaGetSymbolAddress((void**)&p_w,  g_w16);
    cudaGetSymbolAddress((void**)&p_cc, g_cc16);

    cudaFuncSetAttribute(gemm_h<0>, cudaFuncAttributeMaxDynamicSharedMemorySize,
                         GEMM_SMEM_BYTES);
    cudaFuncSetAttribute(gemm_h<1>, cudaFuncAttributeMaxDynamicSharedMemorySize,
                         GEMM_SMEM_BYTES);
    cudaFuncSetAttribute(attn_mma, cudaFuncAttributeMaxDynamicSharedMemorySize,
                         ATTN_SMEM_BYTES);

    const int XW = BB*SS*EE/2;    // words per input tensor
    const int WW = EE*HD/2;       // words per weight

    // ---- fp32 -> fp16 conversions ----
    cvtk<<<(BB*SS*EE/4 + 255)/256, 256>>>((const float4*)q,  (uint2*)(p_x),            BB*SS*EE/4);
    cvtk<<<(BB*SS*EE/4 + 255)/256, 256>>>((const float4*)k,  (uint2*)(p_x + XW),       BB*SS*EE/4);
    cvtk<<<(BB*SS*EE/4 + 255)/256, 256>>>((const float4*)v,  (uint2*)(p_x + 2*XW),     BB*SS*EE/4);
    cvtk<<<(EE*HD/4 + 255)/256, 256>>>((const float4*)Wq, (uint2*)(p_w),            EE*HD/4);
    cvtk<<<(EE*HD/4 + 255)/256, 256>>>((const float4*)Wk, (uint2*)(p_w + WW),       EE*HD/4);
    cvtk<<<(EE*HD/4 + 255)/256, 256>>>((const float4*)Wv, (uint2*)(p_w + 2*WW),     EE*HD/4);
    cvtk<<<(EE*HD/4 + 255)/256, 256>>>((const float4*)Wo, (uint2*)(p_w + 3*WW),     EE*HD/4);

    dim3 gProj(HD / 128, (BB * SS) / 128);  // (8, 32)
    gemm_h<1><<<gProj, 256, GEMM_SMEM_BYTES>>>(p_x,        p_w,        bq, p_qh, BB*SS, HD, EE);
    gemm_h<1><<<gProj, 256, GEMM_SMEM_BYTES>>>(p_x + XW,   p_w + WW,   bk, p_kh, BB*SS, HD, EE);
    gemm_h<1><<<gProj, 256, GEMM_SMEM_BYTES>>>(p_x + 2*XW, p_w + 2*WW, bv, p_vh, BB*SS, HD, EE);

    dim3 gAttn(SS / 128, HH, BB);           // (16, 16, 2)
    attn_mma<<<gAttn, 256, ATTN_SMEM_BYTES>>>(p_qh, p_kh, p_vh, msk, scores, p_cc);

    dim3 gOut(EE / 128, (BB * SS) / 128);   // (8, 32)
    gemm_h<0><<<gOut, 256, GEMM_SMEM_BYTES>>>(p_cc, p_w + 3*WW, bo, out, BB*SS, EE, HD);
}

// round 11
// speedup vs baseline: 2.2526x; 1.0359x over previous
#include <cuda_runtime.h>
#include <math.h>
#include <stdint.h>

#define BB 2
#define SS 2048
#define EE 1024
#define HH 16
#define DKK 64
#define HD (HH*DKK)   // 1024

// -------- scratch (allocation-free rule: __device__ globals) --------
__device__ uint32_t g_qh16[BB*HH*SS*DKK/2];   // head-layout fp16x2
__device__ uint32_t g_kh16[BB*HH*SS*DKK/2];
__device__ uint32_t g_vh16[BB*HH*SS*DKK/2];
__device__ uint32_t g_x16[3][BB*SS*EE/2];     // q,k,v inputs fp16x2
__device__ uint32_t g_w16[4][EE*HD/2];        // Wq,Wk,Wv,Wo fp16x2
__device__ uint32_t g_cc16[BB*SS*HD/2];       // concat fp16x2

// ===================================================================
// helpers (baseline PTX, works on compute_103)
// ===================================================================
__device__ __forceinline__ void mma_f16(float* d, const uint32_t* a,
                                        const uint32_t* b) {
    asm volatile(
        "mma.sync.aligned.m16n8k16.row.col.f32.f16.f16.f32 "
        "{%0,%1,%2,%3}, {%4,%5,%6,%7}, {%8,%9}, {%0,%1,%2,%3};"
        : "+f"(d[0]), "+f"(d[1]), "+f"(d[2]), "+f"(d[3])
        : "r"(a[0]), "r"(a[1]), "r"(a[2]), "r"(a[3]),
          "r"(b[0]), "r"(b[1]));
}

__device__ __forceinline__ uint32_t pack_h2(float lo, float hi) {
    uint32_t r;
    asm("cvt.rn.f16x2.f32 %0, %1, %2;" : "=r"(r) : "f"(hi), "f"(lo));
    return r;
}

__device__ __forceinline__ void ldm_x4(uint32_t* r, uint32_t saddr) {
    asm volatile(
        "ldmatrix.sync.aligned.m8n8.x4.shared.b16 {%0,%1,%2,%3}, [%4];"
        : "=r"(r[0]), "=r"(r[1]), "=r"(r[2]), "=r"(r[3]) : "r"(saddr));
}

__device__ __forceinline__ void ldm_x4_t(uint32_t* r, uint32_t saddr) {
    asm volatile(
        "ldmatrix.sync.aligned.m8n8.x4.trans.shared.b16 {%0,%1,%2,%3}, [%4];"
        : "=r"(r[0]), "=r"(r[1]), "=r"(r[2]), "=r"(r[3]) : "r"(saddr));
}

__device__ __forceinline__ void cp_async16(uint32_t saddr, const void* gaddr) {
    asm volatile("cp.async.cg.shared.global [%0], [%1], 16;"
                 :: "r"(saddr), "l"(gaddr));
}
#define CP_COMMIT() asm volatile("cp.async.commit_group;" ::: "memory")
#define CP_WAIT0()  asm volatile("cp.async.wait_group 0;" ::: "memory")
#define CP_WAIT1()  asm volatile("cp.async.wait_group 1;" ::: "memory")

__device__ __forceinline__ void stg_cs_v2(float* p, float x, float y) {
    asm volatile("st.global.cs.v2.f32 [%0], {%1,%2};"
                 :: "l"(p), "f"(x), "f"(y) : "memory");
}

// ---- fused fp32 -> packed fp16 conversion: 7 tensors, one launch ----
struct Cvt7 {
    const float4* src[7];
    uint2*        dst[7];
    int           n4[7];
};
__global__ __launch_bounds__(256) void cvtk7(Cvt7 a) {
    int z = blockIdx.y;
    const float4* __restrict__ s = a.src[z];
    uint2* __restrict__ d = a.dst[z];
    int n = a.n4[z];
    for (int i = blockIdx.x * 256 + threadIdx.x; i < n; i += gridDim.x * 256) {
        float4 v = s[i];
        d[i] = make_uint2(pack_h2(v.x, v.y), pack_h2(v.z, v.w));
    }
}

// ===================================================================
// fp16 tensor-core GEMM body (R10-verified), cp.async 3-stage pipeline.
// MODE 0: fp32 row-major store.  MODE 1: fp16x2 head-layout scatter.
// ===================================================================
#define FASTR 20
#define FWSTR 68
#define FABUF (128*FASTR)
#define FWBUF (32*FWSTR)
#define STGW  (FABUF + FWBUF)
#define GEMM_SMEM_BYTES (3 * STGW * 4)   // 56832

template<int MODE>
__device__ __forceinline__
void gemm_body(const uint32_t* __restrict__ A, const uint32_t* __restrict__ W,
               const float* __restrict__ bias, void* __restrict__ Cv,
               int M, int N, int K)
{
    extern __shared__ uint32_t sm[];
    uint32_t smbase = (uint32_t)__cvta_generic_to_shared(sm);

    int tid = threadIdx.x, lane = tid & 31, wid = tid >> 5;
    int bm = blockIdx.y * 128, bn = blockIdx.x * 128;
    int wM = (wid >> 1) * 32, wN = (wid & 1) * 64;
    int g = lane >> 2, c = lane & 3;

    float acc[2][8][4];
#pragma unroll
    for (int mf = 0; mf < 2; mf++)
#pragma unroll
        for (int nf = 0; nf < 8; nf++)
#pragma unroll
            for (int r = 0; r < 4; r++) acc[mf][nf][r] = 0.f;

    const int NC = K / 32;
    const int Kw = K / 2, Nw = N / 2;

    int aRow[2], aW4[2], wRow[2], wW4[2];
#pragma unroll
    for (int i = 0; i < 2; i++) {
        int idx = tid + i * 256;
        aRow[i] = idx >> 2;  aW4[i] = idx & 3;
        wRow[i] = idx >> 4;  wW4[i] = idx & 15;
    }

    int ldrow = (lane & 7) + 8 * ((lane >> 3) & 1);
    int ahalf = 4 * (lane >> 4);

    auto stage = [&](int ci, int s) {
        uint32_t aOff = smbase + (s * STGW) * 4;
        uint32_t bOff = aOff + FABUF * 4;
#pragma unroll
        for (int i = 0; i < 2; i++) {
            cp_async16(aOff + (aRow[i] * FASTR + aW4[i] * 4) * 4,
                       A + (size_t)(bm + aRow[i]) * Kw + ci * 16 + aW4[i] * 4);
            cp_async16(bOff + (wRow[i] * FWSTR + wW4[i] * 4) * 4,
                       W + (size_t)(ci * 32 + wRow[i]) * Nw + bn / 2 + wW4[i] * 4);
        }
        CP_COMMIT();
    };

    stage(0, 0);
    stage(1, 1);

    for (int i = 0; i < NC; i++) {
        int s = i % 3;
        if (i + 2 < NC) { CP_WAIT1(); } else { CP_WAIT0(); }
        __syncthreads();
        if (i + 2 < NC) stage(i + 2, (i + 2) % 3);

        uint32_t aBase = smbase + (s * STGW + (wM + ldrow) * FASTR + ahalf) * 4;
        uint32_t bBase = smbase + (s * STGW + FABUF + ldrow * FWSTR + wN/2 + ahalf) * 4;
#pragma unroll
        for (int ks = 0; ks < 2; ks++) {
            uint32_t af[2][4];
            ldm_x4(af[0], aBase + ks * 32);
            ldm_x4(af[1], aBase + 16 * FASTR * 4 + ks * 32);
#pragma unroll
            for (int nfp = 0; nfp < 4; nfp++) {
                uint32_t bf[4];
                ldm_x4_t(bf, bBase + ks * (16 * FWSTR * 4) + nfp * 32);
                mma_f16(acc[0][2*nfp    ], af[0], bf + 0);
                mma_f16(acc[0][2*nfp + 1], af[0], bf + 2);
                mma_f16(acc[1][2*nfp    ], af[1], bf + 0);
                mma_f16(acc[1][2*nfp + 1], af[1], bf + 2);
            }
        }
        __syncthreads();
    }

#pragma unroll
    for (int nf = 0; nf < 8; nf++) {
        int col = bn + wN + nf * 8 + 2 * c;
        float b0 = bias[col], b1 = bias[col + 1];
#pragma unroll
        for (int mf = 0; mf < 2; mf++) {
            int row = bm + wM + mf * 16 + g;
#pragma unroll
            for (int half = 0; half < 2; half++) {
                int r = row + half * 8;
                float wx = acc[mf][nf][half * 2 + 0] + b0;
                float wy = acc[mf][nf][half * 2 + 1] + b1;
                if (MODE == 0) {
                    float2 w = { wx, wy };
                    *(float2*)((float*)Cv + (size_t)r * N + col) = w;
                } else {
                    int bI = r >> 11, sI = r & 2047;
                    int hI = col >> 6, dI = col & 63;
                    uint32_t* dst = (uint32_t*)Cv +
                        (((size_t)(bI * HH + hI) * SS + sI) * (DKK/2) + (dI >> 1));
                    *dst = pack_h2(wx, wy);
                }
            }
        }
    }
}

// MODE-0 wrapper: output projection
__global__ __launch_bounds__(256)
void gemm_out(const uint32_t* __restrict__ A, const uint32_t* __restrict__ W,
              const float* __restrict__ bias, float* __restrict__ C,
              int M, int N, int K)
{
    gemm_body<0>(A, W, bias, C, M, N, K);
}

// MODE-1 wrapper: all three projections in one launch (blockIdx.z)
struct Proj3 {
    const uint32_t* A[3];
    const uint32_t* W[3];
    const float*    bias[3];
    uint32_t*       C[3];
};
__global__ __launch_bounds__(256)
void gemm_proj(Proj3 p, int M, int N, int K)
{
    int z = blockIdx.z;
    gemm_body<1>(p.A[z], p.W[z], p.bias[z], p.C[z], M, N, K);
}

// ===================================================================
// Tensor-core flash attention (R10-verified) — fp16 + cp.async pipeline.
// Change vs R10: scores stored with .cs (streaming) hint.
// ===================================================================
#define HSTR 36
#define KOFF  (128*HSTR)
#define KVBUF (64*HSTR)
#define VOFF  (KOFF + 2*KVBUF)
#define MOFF  (VOFF + 2*KVBUF)
#define ATTN_SMEM_BYTES ((MOFF + 128) * 4)   // 55808

__global__ __launch_bounds__(256, 2)
void attn_mma(const uint32_t* __restrict__ qh, const uint32_t* __restrict__ kh,
              const uint32_t* __restrict__ vh, const int* __restrict__ mask,
              float* __restrict__ scores, uint32_t* __restrict__ concat)
{
    extern __shared__ uint32_t sm[];
    uint32_t* Qs = sm;
    int*      Mk = (int*)(sm + MOFF);
    uint32_t smbase = (uint32_t)__cvta_generic_to_shared(sm);

    int tid = threadIdx.x, lane = tid & 31, wid = tid >> 5;
    int g = lane >> 2, c = lane & 3;
    int q0 = blockIdx.x * 128;
    int h = blockIdx.y, b = blockIdx.z;
    int wq = wid * 16;

    const uint4* Qg4 = (const uint4*)(qh + (size_t)(b * HH + h) * SS * 32) + (size_t)q0 * 8;
    const uint4* Kg4 = (const uint4*)(kh + (size_t)(b * HH + h) * SS * 32);
    const uint4* Vg4 = (const uint4*)(vh + (size_t)(b * HH + h) * SS * 32);
    float* scb = scores + ((size_t)(b * HH + h) * SS + q0) * SS;

#pragma unroll
    for (int i = 0; i < 4; i++) {
        int idx = tid + i * 256;
        int row = idx >> 3, w4 = idx & 7;
        *(uint4*)(Qs + row * HSTR + w4 * 4) = Qg4[row * 8 + w4];
    }

    int cprow[2], cpw4[2];
#pragma unroll
    for (int i = 0; i < 2; i++) {
        int idx = tid + i * 256;
        cprow[i] = idx >> 3; cpw4[i] = idx & 7;
    }

#pragma unroll
    for (int i = 0; i < 2; i++) {
        uint32_t ks_ = smbase + (KOFF + cprow[i] * HSTR + cpw4[i] * 4) * 4;
        cp_async16(ks_, Kg4 + cprow[i] * 8 + cpw4[i]);
        uint32_t vs_ = smbase + (VOFF + cprow[i] * HSTR + cpw4[i] * 4) * 4;
        cp_async16(vs_, Vg4 + cprow[i] * 8 + cpw4[i]);
    }
    CP_COMMIT();
    int mkR = (tid < 64) ? mask[b * SS + tid] : 0;

    int qrow  = wq + (lane & 7) + 8 * ((lane >> 3) & 1);
    int qcsel = 4 * (lane >> 4);
    uint32_t qaddr = smbase + (qrow * HSTR + qcsel) * 4;

    int krowoff = (lane & 7) + 8 * (lane >> 4);
    int kwsel   = 4 * ((lane >> 3) & 1);
    uint32_t kLane = (uint32_t)(krowoff * HSTR + kwsel) * 4;

    int vrowoff = (lane & 7) + 8 * ((lane >> 3) & 1);
    int vwsel   = 4 * (lane >> 4);
    uint32_t vLane = (uint32_t)(vrowoff * HSTR + vwsel) * 4;

    float m0 = -INFINITY, m1 = -INFINITY, l0 = 0.f, l1 = 0.f;
    float o[8][4];
#pragma unroll
    for (int nf = 0; nf < 8; nf++)
#pragma unroll
        for (int r = 0; r < 4; r++) o[nf][r] = 0.f;

    int rowA = wq + g;

    for (int it = 0; it < SS / 64; it++) {
        int buf = it & 1;
        int kv0 = it * 64;
        CP_WAIT0();
        if (tid < 64) Mk[buf * 64 + tid] = mkR;
        __syncthreads();

        if (it + 1 < SS / 64) {
            int nbase = (it + 1) * 64;
#pragma unroll
            for (int i = 0; i < 2; i++) {
                uint32_t ks_ = smbase + (KOFF + (buf ^ 1) * KVBUF
                                         + cprow[i] * HSTR + cpw4[i] * 4) * 4;
                cp_async16(ks_, Kg4 + (nbase + cprow[i]) * 8 + cpw4[i]);
                uint32_t vs_ = smbase + (VOFF + (buf ^ 1) * KVBUF
                                         + cprow[i] * HSTR + cpw4[i] * 4) * 4;
                cp_async16(vs_, Vg4 + (nbase + cprow[i]) * 8 + cpw4[i]);
            }
            CP_COMMIT();
            mkR = (tid < 64) ? mask[b * SS + nbase + tid] : 0;
        }

        uint32_t kaddr0 = smbase + (KOFF + buf * KVBUF) * 4 + kLane;
        uint32_t vaddr0 = smbase + (VOFF + buf * KVBUF) * 4 + vLane;
        const int* MkB = Mk + buf * 64;

        float s[8][4];
#pragma unroll
        for (int nf = 0; nf < 8; nf++)
#pragma unroll
            for (int r = 0; r < 4; r++) s[nf][r] = 0.f;

#pragma unroll
        for (int ks = 0; ks < 4; ks++) {
            uint32_t aq[4];
            ldm_x4(aq, qaddr + ks * 32);
#pragma unroll
            for (int nfp = 0; nfp < 4; nfp++) {
                uint32_t kb[4];
                ldm_x4(kb, kaddr0 + nfp * (16 * HSTR * 4) + ks * 32);
                mma_f16(s[2*nfp    ], aq, kb + 0);
                mma_f16(s[2*nfp + 1], aq, kb + 2);
            }
        }

        float mx0 = -INFINITY, mx1 = -INFINITY;
#pragma unroll
        for (int nf = 0; nf < 8; nf++) {
            int col = nf * 8 + 2 * c;
            int2 mv = *(const int2*)(MkB + col);
            s[nf][0] = mv.x ? s[nf][0] * 0.125f : -1e9f;
            s[nf][1] = mv.y ? s[nf][1] * 0.125f : -1e9f;
            s[nf][2] = mv.x ? s[nf][2] * 0.125f : -1e9f;
            s[nf][3] = mv.y ? s[nf][3] * 0.125f : -1e9f;
            stg_cs_v2(scb + (size_t)(rowA    ) * SS + kv0 + col, s[nf][0], s[nf][1]);
            stg_cs_v2(scb + (size_t)(rowA + 8) * SS + kv0 + col, s[nf][2], s[nf][3]);
            mx0 = fmaxf(mx0, fmaxf(s[nf][0], s[nf][1]));
            mx1 = fmaxf(mx1, fmaxf(s[nf][2], s[nf][3]));
        }
        mx0 = fmaxf(mx0, __shfl_xor_sync(0xFFFFFFFFu, mx0, 1));
        mx0 = fmaxf(mx0, __shfl_xor_sync(0xFFFFFFFFu, mx0, 2));
        mx1 = fmaxf(mx1, __shfl_xor_sync(0xFFFFFFFFu, mx1, 1));
        mx1 = fmaxf(mx1, __shfl_xor_sync(0xFFFFFFFFu, mx1, 2));

        float mn0 = fmaxf(m0, mx0), mn1 = fmaxf(m1, mx1);
        float a0 = __expf(m0 - mn0), a1 = __expf(m1 - mn1);
        m0 = mn0; m1 = mn1;

        float sum0 = 0.f, sum1 = 0.f;
#pragma unroll
        for (int nf = 0; nf < 8; nf++) {
            s[nf][0] = __expf(s[nf][0] - mn0);
            s[nf][1] = __expf(s[nf][1] - mn0);
            s[nf][2] = __expf(s[nf][2] - mn1);
            s[nf][3] = __expf(s[nf][3] - mn1);
            sum0 += s[nf][0] + s[nf][1];
            sum1 += s[nf][2] + s[nf][3];
        }
        sum0 += __shfl_xor_sync(0xFFFFFFFFu, sum0, 1);
        sum0 += __shfl_xor_sync(0xFFFFFFFFu, sum0, 2);
        sum1 += __shfl_xor_sync(0xFFFFFFFFu, sum1, 1);
        sum1 += __shfl_xor_sync(0xFFFFFFFFu, sum1, 2);
        l0 = l0 * a0 + sum0;
        l1 = l1 * a1 + sum1;

#pragma unroll
        for (int nf = 0; nf < 8; nf++) {
            o[nf][0] *= a0; o[nf][1] *= a0;
            o[nf][2] *= a1; o[nf][3] *= a1;
        }

#pragma unroll
        for (int ks = 0; ks < 4; ks++) {
            uint32_t ap[4];
            ap[0] = pack_h2(s[2*ks    ][0], s[2*ks    ][1]);
            ap[1] = pack_h2(s[2*ks    ][2], s[2*ks    ][3]);
            ap[2] = pack_h2(s[2*ks + 1][0], s[2*ks + 1][1]);
            ap[3] = pack_h2(s[2*ks + 1][2], s[2*ks + 1][3]);
#pragma unroll
            for (int nfp = 0; nfp < 4; nfp++) {
                uint32_t vb[4];
                ldm_x4_t(vb, vaddr0 + ks * (16 * HSTR * 4) + nfp * 32);
                mma_f16(o[2*nfp    ], ap, vb + 0);
                mma_f16(o[2*nfp + 1], ap, vb + 2);
            }
        }
    }

    float inv0 = 1.f / l0, inv1 = 1.f / l1;
#pragma unroll
    for (int nf = 0; nf < 8; nf++) {
        int d = nf * 8 + 2 * c;
        size_t w0i = (size_t)(b * SS + q0 + rowA    ) * (HD/2) + (h * DKK + d) / 2;
        size_t w1i = (size_t)(b * SS + q0 + rowA + 8) * (HD/2) + (h * DKK + d) / 2;
        concat[w0i] = pack_h2(o[nf][0] * inv0, o[nf][1] * inv0);
        concat[w1i] = pack_h2(o[nf][2] * inv1, o[nf][3] * inv1);
    }
}

// ===================================================================
extern "C" void kernel_launch(void* const* d_in, const int* in_sizes, int n_in,
                              void* d_out, int out_size)
{
    const float* q   = (const float*)d_in[0];
    const float* k   = (const float*)d_in[1];
    const float* v   = (const float*)d_in[2];
    const int*   msk = (const int*)  d_in[3];
    const float* Wq  = (const float*)d_in[4];
    const float* bq  = (const float*)d_in[5];
    const float* Wk  = (const float*)d_in[6];
    const float* bk  = (const float*)d_in[7];
    const float* Wv  = (const float*)d_in[8];
    const float* bv  = (const float*)d_in[9];
    const float* Wo  = (const float*)d_in[10];
    const float* bo  = (const float*)d_in[11];

    float* out    = (float*)d_out;              // (B,S,E)
    float* scores = out + (size_t)BB * SS * EE; // (B,H,S,S)

    uint32_t *p_qh, *p_kh, *p_vh, *p_x, *p_w, *p_cc;
    cudaGetSymbolAddress((void**)&p_qh, g_qh16);
    cudaGetSymbolAddress((void**)&p_kh, g_kh16);
    cudaGetSymbolAddress((void**)&p_vh, g_vh16);
    cudaGetSymbolAddress((void**)&p_x,  g_x16);
    cudaGetSymbolAddress((void**)&p_w,  g_w16);
    cudaGetSymbolAddress((void**)&p_cc, g_cc16);

    cudaFuncSetAttribute(gemm_out, cudaFuncAttributeMaxDynamicSharedMemorySize,
                         GEMM_SMEM_BYTES);
    cudaFuncSetAttribute(gemm_proj, cudaFuncAttributeMaxDynamicSharedMemorySize,
                         GEMM_SMEM_BYTES);
    cudaFuncSetAttribute(attn_mma, cudaFuncAttributeMaxDynamicSharedMemorySize,
                         ATTN_SMEM_BYTES);

    const int XW = BB*SS*EE/2;    // words per input tensor
    const int WW = EE*HD/2;       // words per weight
    const int XN4 = BB*SS*EE/4;   // float4 count per input
    const int WN4 = EE*HD/4;      // float4 count per weight

    // ---- fused fp32 -> fp16 conversions (one launch, 7 slices) ----
    Cvt7 ca;
    ca.src[0] = (const float4*)q;  ca.dst[0] = (uint2*)(p_x);          ca.n4[0] = XN4;
    ca.src[1] = (const float4*)k;  ca.dst[1] = (uint2*)(p_x + XW);     ca.n4[1] = XN4;
    ca.src[2] = (const float4*)v;  ca.dst[2] = (uint2*)(p_x + 2*XW);   ca.n4[2] = XN4;
    ca.src[3] = (const float4*)Wq; ca.dst[3] = (uint2*)(p_w);          ca.n4[3] = WN4;
    ca.src[4] = (const float4*)Wk; ca.dst[4] = (uint2*)(p_w + WW);     ca.n4[4] = WN4;
    ca.src[5] = (const float4*)Wv; ca.dst[5] = (uint2*)(p_w + 2*WW);   ca.n4[5] = WN4;
    ca.src[6] = (const float4*)Wo; ca.dst[6] = (uint2*)(p_w + 3*WW);   ca.n4[6] = WN4;
    cvtk7<<<dim3(512, 7), 256>>>(ca);

    // ---- three projection GEMMs in one launch ----
    Proj3 pa;
    pa.A[0] = p_x;          pa.W[0] = p_w;          pa.bias[0] = bq; pa.C[0] = p_qh;
    pa.A[1] = p_x + XW;     pa.W[1] = p_w + WW;     pa.bias[1] = bk; pa.C[1] = p_kh;
    pa.A[2] = p_x + 2*XW;   pa.W[2] = p_w + 2*WW;   pa.bias[2] = bv; pa.C[2] = p_vh;
    dim3 gProj(HD / 128, (BB * SS) / 128, 3);  // (8, 32, 3)
    gemm_proj<<<gProj, 256, GEMM_SMEM_BYTES>>>(pa, BB*SS, HD, EE);

    dim3 gAttn(SS / 128, HH, BB);              // (16, 16, 2)
    attn_mma<<<gAttn, 256, ATTN_SMEM_BYTES>>>(p_qh, p_kh, p_vh, msk, scores, p_cc);

    dim3 gOut(EE / 128, (BB * SS) / 128);      // (8, 32)
    gemm_out<<<gOut, 256, GEMM_SMEM_BYTES>>>(p_cc, p_w + 3*WW, bo, out, BB*SS, EE, HD);
}